// round 1
// baseline (speedup 1.0000x reference)
#include <cuda_runtime.h>
#include <math.h>

// Problem constants
#define BB   8
#define TT   8
#define HH   14
#define WW   14
#define SPA  1568          // T*H*W
#define MTOT 12544         // B*SPA

// ---------------- scratch (device globals; no allocation allowed) -------------
__device__ float g_xT [(size_t)MTOT * 832];   // x channels-last
__device__ float g_xmT[(size_t)MTOT * 832];   // maxpool(x) channels-last
__device__ float g_x1a[(size_t)MTOT * 160];   // branch1 intermediate (channels-last)
__device__ float g_x2a[(size_t)MTOT * 32];    // branch2 intermediate (channels-last)
__device__ float g_samp[(size_t)MTOT * 4320]; // im2col / sampled rows (max layer2)
__device__ float g_conv[(size_t)MTOT * 320];  // raw conv output (max layer2)
__device__ float g_offb[(size_t)MTOT * 81];   // offset field (max layer2)
__device__ float g_stats[1024];               // [0..511]=mean, [512..1023]=var
__device__ float g_wT  [1972224];             // transposed main-conv weights (all 6)
__device__ float g_woffT[430000];             // transposed offset-conv weights (all 6)

// ---------------- transpose x: [B,C,SPA] -> [B,SPA,C] (C=832) -----------------
__global__ void k_transpose_cl(const float* __restrict__ in, float* __restrict__ out) {
    __shared__ float tile[32][33];
    int b  = blockIdx.z;
    int s0 = blockIdx.x * 32;
    int c0 = blockIdx.y * 32;
    int tx = threadIdx.x, ty = threadIdx.y;
    #pragma unroll
    for (int i = ty; i < 32; i += 8)
        tile[i][tx] = in[((size_t)b * 832 + (c0 + i)) * SPA + s0 + tx];
    __syncthreads();
    #pragma unroll
    for (int i = ty; i < 32; i += 8)
        out[((size_t)b * SPA + (s0 + i)) * 832 + c0 + tx] = tile[tx][i];
}

// ---------------- 3x3x3 maxpool, stride 1, pad 1, channels-last ---------------
__global__ void k_maxpool(const float* __restrict__ in, float* __restrict__ out) {
    int m = blockIdx.x;
    int b = m / SPA, s = m - b * SPA;
    int t = s / (HH * WW); int rem = s - t * HH * WW;
    int h = rem / WW, w = rem - h * WW;
    for (int c = threadIdx.x; c < 832; c += blockDim.x) {
        float v = -INFINITY;
        for (int dt = -1; dt <= 1; dt++) {
            int tt = t + dt; if (tt < 0 || tt >= TT) continue;
            for (int dh = -1; dh <= 1; dh++) {
                int hh2 = h + dh; if (hh2 < 0 || hh2 >= HH) continue;
                for (int dw = -1; dw <= 1; dw++) {
                    int ww2 = w + dw; if (ww2 < 0 || ww2 >= WW) continue;
                    v = fmaxf(v, in[((size_t)b * SPA + (tt * HH + hh2) * WW + ww2) * 832 + c]);
                }
            }
        }
        out[(size_t)m * 832 + c] = v;
    }
}

// ---------------- weight transpose: w[Cout,Cin,K] -> wT[(k*Cin+c)*Cout+oc] ----
__global__ void k_wtrans(const float* __restrict__ w, float* __restrict__ wT,
                         int Cout, int Cin, int K) {
    int idx = blockIdx.x * blockDim.x + threadIdx.x;
    int tot = Cout * Cin * K;
    if (idx >= tot) return;
    int oc = idx % Cout; int rest = idx / Cout;
    int c  = rest % Cin; int kk = rest / Cin;
    wT[idx] = w[((size_t)oc * Cin + c) * K + kk];
}

// ---------------- tiled SGEMM: C[M,N] = A[M,K] @ B[K,N] (+bias) ---------------
// M = MTOT (multiple of 64), K multiple of 16 & 4, N arbitrary (guarded).
__global__ void k_gemm(const float* __restrict__ A, const float* __restrict__ Bm,
                       const float* __restrict__ bias, float* __restrict__ Cc,
                       int Nn, int Kn) {
    __shared__ float As[16][65];
    __shared__ float Bs[16][64];
    int tid = threadIdx.x;
    int tx = tid & 15, ty = tid >> 4;
    int m0 = blockIdx.y * 64, n0 = blockIdx.x * 64;
    float acc[4][4] = {};
    for (int k0 = 0; k0 < Kn; k0 += 16) {
        int r  = tid >> 2;
        int cc = (tid & 3) << 2;
        float4 va = *reinterpret_cast<const float4*>(&A[(size_t)(m0 + r) * Kn + k0 + cc]);
        As[cc + 0][r] = va.x; As[cc + 1][r] = va.y;
        As[cc + 2][r] = va.z; As[cc + 3][r] = va.w;
        int kb = tid >> 4;
        int nb = (tid & 15) << 2;
        #pragma unroll
        for (int i = 0; i < 4; i++) {
            int n = n0 + nb + i;
            Bs[kb][nb + i] = (n < Nn) ? Bm[(size_t)(k0 + kb) * Nn + n] : 0.f;
        }
        __syncthreads();
        #pragma unroll
        for (int kk = 0; kk < 16; kk++) {
            float a[4], b[4];
            #pragma unroll
            for (int i = 0; i < 4; i++) a[i] = As[kk][ty * 4 + i];
            #pragma unroll
            for (int i = 0; i < 4; i++) b[i] = Bs[kk][tx * 4 + i];
            #pragma unroll
            for (int i = 0; i < 4; i++)
                #pragma unroll
                for (int j = 0; j < 4; j++)
                    acc[i][j] = fmaf(a[i], b[j], acc[i][j]);
        }
        __syncthreads();
    }
    #pragma unroll
    for (int i = 0; i < 4; i++) {
        int m = m0 + ty * 4 + i;
        #pragma unroll
        for (int j = 0; j < 4; j++) {
            int n = n0 + tx * 4 + j;
            if (n < Nn) {
                float v = acc[i][j];
                if (bias) v += bias[n];
                Cc[(size_t)m * Nn + n] = v;
            }
        }
    }
}

// ---------------- trilinear sampling: samp[m][kk][c] --------------------------
__global__ void k_sample(const float* __restrict__ src, const float* __restrict__ off,
                         float* __restrict__ samp, int C, int k, int pad) {
    int m  = blockIdx.x;
    int kk = blockIdx.y;
    int K  = gridDim.y;
    int b = m / SPA, s = m - b * SPA;
    int t = s / (HH * WW); int rem = s - t * HH * WW;
    int h = rem / WW, w = rem - h * WW;
    int kt = kk / (k * k), kh = (kk / k) % k, kw = kk % k;
    const float* op = off + (size_t)m * 3 * K + kk * 3;
    float tc = (float)(t - pad + kt) + op[0];
    float hc = (float)(h - pad + kh) + op[1];
    float wc = (float)(w - pad + kw) + op[2];
    float tf = floorf(tc), hf = floorf(hc), wf = floorf(wc);
    float ft = tc - tf, fh = hc - hf, fw = wc - wf;
    int t0 = (int)tf, h0 = (int)hf, w0 = (int)wf;

    float wgt[8]; const float* ptr[8];
    #pragma unroll
    for (int ci = 0; ci < 8; ci++) {
        int dt = ci >> 2, dh = (ci >> 1) & 1, dw = ci & 1;
        int ti = t0 + dt, hi = h0 + dh, wi = w0 + dw;
        bool valid = (ti >= 0) && (ti < TT) && (hi >= 0) && (hi < HH) && (wi >= 0) && (wi < WW);
        float wv = (dt ? ft : 1.f - ft) * (dh ? fh : 1.f - fh) * (dw ? fw : 1.f - fw);
        wgt[ci] = valid ? wv : 0.f;
        int tic = min(max(ti, 0), TT - 1);
        int hic = min(max(hi, 0), HH - 1);
        int wic = min(max(wi, 0), WW - 1);
        ptr[ci] = src + ((size_t)b * SPA + (tic * HH + hic) * WW + wic) * C;
    }
    float* dst = samp + ((size_t)m * K + kk) * C;
    for (int c = threadIdx.x * 4; c < C; c += blockDim.x * 4) {
        float4 acc = make_float4(0.f, 0.f, 0.f, 0.f);
        #pragma unroll
        for (int ci = 0; ci < 8; ci++) {
            float4 v = *reinterpret_cast<const float4*>(ptr[ci] + c);
            acc.x = fmaf(wgt[ci], v.x, acc.x);
            acc.y = fmaf(wgt[ci], v.y, acc.y);
            acc.z = fmaf(wgt[ci], v.z, acc.z);
            acc.w = fmaf(wgt[ci], v.w, acc.w);
        }
        *reinterpret_cast<float4*>(dst + c) = acc;
    }
}

// ---------------- im2col (k=3, pad=1, integer taps) ---------------------------
__global__ void k_im2col(const float* __restrict__ src, float* __restrict__ outm, int C) {
    int m  = blockIdx.x;
    int kk = blockIdx.y;
    int K  = gridDim.y;
    int b = m / SPA, s = m - b * SPA;
    int t = s / (HH * WW); int rem = s - t * HH * WW;
    int h = rem / WW, w = rem - h * WW;
    int kt = kk / 9, kh = (kk / 3) % 3, kw = kk % 3;
    int ti = t + kt - 1, hi = h + kh - 1, wi = w + kw - 1;
    bool valid = (ti >= 0) && (ti < TT) && (hi >= 0) && (hi < HH) && (wi >= 0) && (wi < WW);
    int sidx = valid ? (ti * HH + hi) * WW + wi : 0;
    const float* sp = src + ((size_t)b * SPA + sidx) * C;
    float* dst = outm + ((size_t)m * K + kk) * C;
    for (int c = threadIdx.x * 4; c < C; c += blockDim.x * 4) {
        float4 v = valid ? *reinterpret_cast<const float4*>(sp + c)
                         : make_float4(0.f, 0.f, 0.f, 0.f);
        *reinterpret_cast<float4*>(dst + c) = v;
    }
}

// ---------------- per-channel batch stats (mean, biased var) ------------------
__global__ void k_stats(const float* __restrict__ Cm, float* __restrict__ stats, int Nn) {
    int n = blockIdx.x * 32 + threadIdx.x;
    float s = 0.f, s2 = 0.f;
    if (n < Nn) {
        for (int m = threadIdx.y; m < MTOT; m += 8) {
            float v = Cm[(size_t)m * Nn + n];
            s += v; s2 += v * v;
        }
    }
    __shared__ float sh[8][32], sh2[8][32];
    sh[threadIdx.y][threadIdx.x] = s;
    sh2[threadIdx.y][threadIdx.x] = s2;
    __syncthreads();
    if (threadIdx.y == 0 && n < Nn) {
        #pragma unroll
        for (int i = 1; i < 8; i++) { s += sh[i][threadIdx.x]; s2 += sh2[i][threadIdx.x]; }
        float mean = s / (float)MTOT;
        float var  = s2 / (float)MTOT - mean * mean;
        stats[n]       = mean;
        stats[512 + n] = var;
    }
}

// ---------------- BN + ReLU + layout write ------------------------------------
// mode 0: write channels-last [m][n] (same layout as Cm)
// mode 1: scatter into d_out [B, 832, SPA] at channel offset ch0 (coalesced on s)
__global__ void k_bnout(const float* __restrict__ Cm, const float* __restrict__ stats,
                        const float* __restrict__ gamma, const float* __restrict__ beta,
                        float* __restrict__ outp, int Nn, int mode, int ch0) {
    size_t idx = (size_t)blockIdx.x * blockDim.x + threadIdx.x;
    size_t tot = (size_t)MTOT * Nn;
    if (idx >= tot) return;
    if (mode == 0) {
        int n = (int)(idx % Nn);
        float sc = gamma[n] * rsqrtf(stats[512 + n] + 1e-5f);
        float v  = fmaf(Cm[idx] - stats[n], sc, beta[n]);
        outp[idx] = fmaxf(v, 0.f);
    } else {
        int s = (int)(idx % SPA); size_t rest = idx / SPA;
        int n = (int)(rest % Nn); int b = (int)(rest / Nn);
        float sc = gamma[n] * rsqrtf(stats[512 + n] + 1e-5f);
        float v  = fmaf(Cm[((size_t)b * SPA + s) * Nn + n] - stats[n], sc, beta[n]);
        outp[((size_t)b * 832 + ch0 + n) * SPA + s] = fmaxf(v, 0.f);
    }
}

// ============================ host orchestration ==============================
static void run_gemm(const float* A, const float* Bm, const float* bias,
                     float* C, int Nn, int Kn) {
    dim3 grid((Nn + 63) / 64, MTOT / 64);
    k_gemm<<<grid, 256>>>(A, Bm, bias, C, Nn, Kn);
}

static int sample_block(int C) { return C >= 512 ? 128 : (C >= 128 ? 64 : 32); }

static void run_k1(const float* srcT, int Cin, int Cout,
                   const float* woffT, const float* boffp, const float* wTp,
                   const float* g, const float* bt,
                   float* offb, float* samp, float* conv, float* stats,
                   float* outp, int mode, int ch0) {
    run_gemm(srcT, woffT, boffp, offb, 3, Cin);
    k_sample<<<dim3(MTOT, 1), sample_block(Cin)>>>(srcT, offb, samp, Cin, 1, 0);
    run_gemm(samp, wTp, nullptr, conv, Cout, Cin);
    k_stats<<<(Cout + 31) / 32, dim3(32, 8)>>>(conv, stats, Cout);
    size_t tot = (size_t)MTOT * Cout;
    k_bnout<<<(unsigned)((tot + 255) / 256), 256>>>(conv, stats, g, bt, outp, Cout, mode, ch0);
}

static void run_k3(const float* srcT, int Cin, int Cout,
                   const float* woffT, const float* boffp, const float* wTp,
                   const float* g, const float* bt,
                   float* offb, float* samp, float* conv, float* stats,
                   float* outp, int mode, int ch0) {
    int Kd = 27 * Cin;
    k_im2col<<<dim3(MTOT, 27), sample_block(Cin)>>>(srcT, samp, Cin);
    run_gemm(samp, woffT, boffp, offb, 81, Kd);
    k_sample<<<dim3(MTOT, 27), sample_block(Cin)>>>(srcT, offb, samp, Cin, 3, 1);
    run_gemm(samp, wTp, nullptr, conv, Cout, Kd);
    k_stats<<<(Cout + 31) / 32, dim3(32, 8)>>>(conv, stats, Cout);
    size_t tot = (size_t)MTOT * Cout;
    k_bnout<<<(unsigned)((tot + 255) / 256), 256>>>(conv, stats, g, bt, outp, Cout, mode, ch0);
}

extern "C" void kernel_launch(void* const* d_in, const int* in_sizes, int n_in,
                              void* d_out, int out_size) {
    const float* x = (const float*)d_in[0];
    const float *woff[6], *boff[6], *wcv[6], *gam[6], *bet[6];
    for (int i = 0; i < 6; i++) {
        woff[i] = (const float*)d_in[1 + 5 * i];
        boff[i] = (const float*)d_in[2 + 5 * i];
        wcv[i]  = (const float*)d_in[3 + 5 * i];
        gam[i]  = (const float*)d_in[4 + 5 * i];
        bet[i]  = (const float*)d_in[5 + 5 * i];
    }
    float *xT, *xmT, *x1a, *x2a, *samp, *conv, *offb, *stats, *wT, *woffT;
    cudaGetSymbolAddress((void**)&xT,    g_xT);
    cudaGetSymbolAddress((void**)&xmT,   g_xmT);
    cudaGetSymbolAddress((void**)&x1a,   g_x1a);
    cudaGetSymbolAddress((void**)&x2a,   g_x2a);
    cudaGetSymbolAddress((void**)&samp,  g_samp);
    cudaGetSymbolAddress((void**)&conv,  g_conv);
    cudaGetSymbolAddress((void**)&offb,  g_offb);
    cudaGetSymbolAddress((void**)&stats, g_stats);
    cudaGetSymbolAddress((void**)&wT,    g_wT);
    cudaGetSymbolAddress((void**)&woffT, g_woffT);
    float* out = (float*)d_out;

    // 1) channels-last x, maxpool
    k_transpose_cl<<<dim3(SPA / 32, 832 / 32, BB), dim3(32, 8)>>>(x, xT);
    k_maxpool<<<MTOT, 256>>>(xT, xmT);

    // 2) weight transposes (wT: [k*Cin+c][Cout]; woffT: [k*Cin+c][3K])
    const int CIN[6]  = {832, 832, 160, 832, 32, 832};
    const int COUT[6] = {256, 160, 320, 32, 128, 128};
    const int KK[6]   = {1, 1, 27, 1, 27, 1};
    size_t wtoff[6], wooff[6];
    {
        size_t a = 0, bsz = 0;
        for (int i = 0; i < 6; i++) { wtoff[i] = a; a += (size_t)KK[i] * CIN[i] * COUT[i]; }
        for (int i = 0; i < 6; i++) { wooff[i] = bsz; bsz += (size_t)KK[i] * CIN[i] * (3 * KK[i]); }
    }
    for (int i = 0; i < 6; i++) {
        int tot1 = KK[i] * CIN[i] * COUT[i];
        k_wtrans<<<(tot1 + 255) / 256, 256>>>(wcv[i], wT + wtoff[i], COUT[i], CIN[i], KK[i]);
        int tot2 = KK[i] * CIN[i] * 3 * KK[i];
        k_wtrans<<<(tot2 + 255) / 256, 256>>>(woff[i], woffT + wooff[i], 3 * KK[i], CIN[i], KK[i]);
    }

    // 3) branch 0: deform(x, 832->256, k=1) -> out channels [0,256)
    run_k1(xT, 832, 256, woffT + wooff[0], boff[0], wT + wtoff[0], gam[0], bet[0],
           offb, samp, conv, stats, out, 1, 0);

    // 4) branch 1: deform(x, 832->160, k=1) -> x1a ; deform(x1a, 160->320, k=3) -> [256,576)
    run_k1(xT, 832, 160, woffT + wooff[1], boff[1], wT + wtoff[1], gam[1], bet[1],
           offb, samp, conv, stats, x1a, 0, 0);
    run_k3(x1a, 160, 320, woffT + wooff[2], boff[2], wT + wtoff[2], gam[2], bet[2],
           offb, samp, conv, stats, out, 1, 256);

    // 5) branch 2: deform(x, 832->32, k=1) -> x2a ; deform(x2a, 32->128, k=3) -> [576,704)
    run_k1(xT, 832, 32, woffT + wooff[3], boff[3], wT + wtoff[3], gam[3], bet[3],
           offb, samp, conv, stats, x2a, 0, 0);
    run_k3(x2a, 32, 128, woffT + wooff[4], boff[4], wT + wtoff[4], gam[4], bet[4],
           offb, samp, conv, stats, out, 1, 576);

    // 6) branch 3: maxpool -> deform(xm, 832->128, k=1) -> [704,832)
    run_k1(xmT, 832, 128, woffT + wooff[5], boff[5], wT + wtoff[5], gam[5], bet[5],
           offb, samp, conv, stats, out, 1, 704);
}

// round 4
// speedup vs baseline: 1.5436x; 1.5436x over previous
#include <cuda_runtime.h>
#include <math.h>
#include <stdint.h>

// Problem constants
#define BB   8
#define TT   8
#define HH   14
#define WW   14
#define SPA  1568          // T*H*W
#define MTOT 12544         // B*SPA

// ---------------- scratch (device globals; no allocation allowed) -------------
__device__ float g_xT [(size_t)MTOT * 832];   // x channels-last
__device__ float g_xmT[(size_t)MTOT * 832];   // maxpool(x) channels-last
__device__ float g_x1a[(size_t)MTOT * 160];   // branch1 intermediate
__device__ float g_x2a[(size_t)MTOT * 32];    // branch2 intermediate
__device__ float g_samp[(size_t)MTOT * 4320]; // im2col / sampled rows (max layer2)
__device__ float g_conv[(size_t)MTOT * 320];  // raw conv output (max layer2)
__device__ float g_offb[(size_t)MTOT * 81];   // offset field (max layer2)
__device__ float g_stats[1024];               // [0..511]=mean, [512..1023]=var
__device__ float g_wT  [1972224];             // transposed main-conv weights
__device__ float g_woffT[430000];             // transposed offset-conv weights

__device__ __forceinline__ uint32_t f2tf(float x) {
    uint32_t u; asm("cvt.rna.tf32.f32 %0, %1;" : "=r"(u) : "f"(x)); return u;
}

// ---------------- transpose x: [B,C,SPA] -> [B,SPA,C] (C=832) -----------------
__global__ void k_transpose_cl(const float* __restrict__ in, float* __restrict__ out) {
    __shared__ float tile[32][33];
    int b  = blockIdx.z;
    int s0 = blockIdx.x * 32;
    int c0 = blockIdx.y * 32;
    int tx = threadIdx.x, ty = threadIdx.y;
    #pragma unroll
    for (int i = ty; i < 32; i += 8)
        tile[i][tx] = in[((size_t)b * 832 + (c0 + i)) * SPA + s0 + tx];
    __syncthreads();
    #pragma unroll
    for (int i = ty; i < 32; i += 8)
        out[((size_t)b * SPA + (s0 + i)) * 832 + c0 + tx] = tile[tx][i];
}

// ---------------- separable 3-max along one dim, channels-last ----------------
__global__ void k_max3(const float* __restrict__ in, float* __restrict__ out,
                       int ddiv, int dmod) {
    size_t idx = (size_t)blockIdx.x * blockDim.x + threadIdx.x;
    if (idx >= (size_t)MTOT * 208) return;
    int c4 = (int)(idx % 208);
    size_t m = idx / 208;
    int s = (int)(m % SPA);
    int coord = (s / ddiv) % dmod;
    const float4* p = reinterpret_cast<const float4*>(in) + m * 208 + c4;
    float4 v = *p;
    if (coord > 0) {
        float4 u = *(p - (size_t)ddiv * 208);
        v.x = fmaxf(v.x, u.x); v.y = fmaxf(v.y, u.y);
        v.z = fmaxf(v.z, u.z); v.w = fmaxf(v.w, u.w);
    }
    if (coord < dmod - 1) {
        float4 u = *(p + (size_t)ddiv * 208);
        v.x = fmaxf(v.x, u.x); v.y = fmaxf(v.y, u.y);
        v.z = fmaxf(v.z, u.z); v.w = fmaxf(v.w, u.w);
    }
    reinterpret_cast<float4*>(out)[m * 208 + c4] = v;
}

// ---------------- weight transpose: w[Cout,Cin,K] -> wT[(k*Cin+c)*Cout+oc] ----
__global__ void k_wtrans(const float* __restrict__ w, float* __restrict__ wT,
                         int Cout, int Cin, int K) {
    int idx = blockIdx.x * blockDim.x + threadIdx.x;
    int tot = Cout * Cin * K;
    if (idx >= tot) return;
    int oc = idx % Cout; int rest = idx / Cout;
    int c  = rest % Cin; int kk = rest / Cin;
    wT[idx] = w[((size_t)oc * Cin + c) * K + kk];
}

// ---------------- tf32 tensor-core GEMM: C[M,N] = A[M,K] @ B[K,N] (+bias) -----
// M = MTOT (mult of 128), K mult of 32, N arbitrary (guarded; vector B loads
// only when Nn % 4 == 0 to keep 16B alignment).
__global__ __launch_bounds__(256) void k_gemm_tf32(
    const float* __restrict__ A, const float* __restrict__ Bm,
    const float* __restrict__ bias, float* __restrict__ Cc, int Nn, int Kn)
{
    __shared__ uint32_t As[32][136];   // [k][m]
    __shared__ uint32_t Bs[32][136];   // [k][n]
    int tid = threadIdx.x;
    int lane = tid & 31, warp = tid >> 5;
    int warpM = warp & 1, warpN = warp >> 1;
    int m0 = blockIdx.y * 128, n0 = blockIdx.x * 128;
    int g = lane >> 2, tg = lane & 3;
    bool vecB = ((Nn & 3) == 0);

    float acc[4][4][4];
    #pragma unroll
    for (int i = 0; i < 4; i++)
        #pragma unroll
        for (int j = 0; j < 4; j++)
            #pragma unroll
            for (int q = 0; q < 4; q++) acc[i][j][q] = 0.f;

    const int mA = tid >> 1;
    const float* aRow = A + (size_t)(m0 + mA) * Kn;
    const int nB = lane * 4;

    for (int k0 = 0; k0 < Kn; k0 += 32) {
        #pragma unroll
        for (int i = 0; i < 4; i++) {
            int kq = (tid & 1) + 2 * i;   // 0..7
            float4 v = *reinterpret_cast<const float4*>(aRow + k0 + kq * 4);
            As[kq * 4 + 0][mA] = f2tf(v.x);
            As[kq * 4 + 1][mA] = f2tf(v.y);
            As[kq * 4 + 2][mA] = f2tf(v.z);
            As[kq * 4 + 3][mA] = f2tf(v.w);
        }
        #pragma unroll
        for (int i = 0; i < 4; i++) {
            int kk = warp + 8 * i;
            const float* bp = Bm + (size_t)(k0 + kk) * Nn;
            float4 v;
            if (vecB && (n0 + nB + 3 < Nn)) {
                v = *reinterpret_cast<const float4*>(bp + n0 + nB);
            } else {
                v.x = (n0 + nB + 0 < Nn) ? bp[n0 + nB + 0] : 0.f;
                v.y = (n0 + nB + 1 < Nn) ? bp[n0 + nB + 1] : 0.f;
                v.z = (n0 + nB + 2 < Nn) ? bp[n0 + nB + 2] : 0.f;
                v.w = (n0 + nB + 3 < Nn) ? bp[n0 + nB + 3] : 0.f;
            }
            Bs[kk][nB + 0] = f2tf(v.x);
            Bs[kk][nB + 1] = f2tf(v.y);
            Bs[kk][nB + 2] = f2tf(v.z);
            Bs[kk][nB + 3] = f2tf(v.w);
        }
        __syncthreads();
        #pragma unroll
        for (int ks = 0; ks < 4; ks++) {
            uint32_t af[4][4], bf[4][2];
            #pragma unroll
            for (int mt = 0; mt < 4; mt++) {
                int mr = warpM * 64 + mt * 16 + g;
                af[mt][0] = As[ks * 8 + tg    ][mr];
                af[mt][1] = As[ks * 8 + tg    ][mr + 8];
                af[mt][2] = As[ks * 8 + tg + 4][mr];
                af[mt][3] = As[ks * 8 + tg + 4][mr + 8];
            }
            #pragma unroll
            for (int nt = 0; nt < 4; nt++) {
                int nc = warpN * 32 + nt * 8 + g;
                bf[nt][0] = Bs[ks * 8 + tg    ][nc];
                bf[nt][1] = Bs[ks * 8 + tg + 4][nc];
            }
            #pragma unroll
            for (int mt = 0; mt < 4; mt++)
                #pragma unroll
                for (int nt = 0; nt < 4; nt++)
                    asm volatile(
                        "mma.sync.aligned.m16n8k8.row.col.f32.tf32.tf32.f32 "
                        "{%0,%1,%2,%3}, {%4,%5,%6,%7}, {%8,%9}, {%0,%1,%2,%3};"
                        : "+f"(acc[mt][nt][0]), "+f"(acc[mt][nt][1]),
                          "+f"(acc[mt][nt][2]), "+f"(acc[mt][nt][3])
                        : "r"(af[mt][0]), "r"(af[mt][1]), "r"(af[mt][2]), "r"(af[mt][3]),
                          "r"(bf[nt][0]), "r"(bf[nt][1]));
        }
        __syncthreads();
    }
    // epilogue (scalar stores, bounds-checked on N)
    #pragma unroll
    for (int mt = 0; mt < 4; mt++) {
        int r0 = m0 + warpM * 64 + mt * 16 + g;
        #pragma unroll
        for (int nt = 0; nt < 4; nt++) {
            int c0 = n0 + warpN * 32 + nt * 8 + tg * 2;
            if (c0 < Nn) {
                float b0 = bias ? bias[c0] : 0.f;
                Cc[(size_t)r0 * Nn + c0]       = acc[mt][nt][0] + b0;
                Cc[(size_t)(r0 + 8) * Nn + c0] = acc[mt][nt][2] + b0;
            }
            if (c0 + 1 < Nn) {
                float b1 = bias ? bias[c0 + 1] : 0.f;
                Cc[(size_t)r0 * Nn + c0 + 1]       = acc[mt][nt][1] + b1;
                Cc[(size_t)(r0 + 8) * Nn + c0 + 1] = acc[mt][nt][3] + b1;
            }
        }
    }
}

// ---------------- dedicated N=3, K=832 GEMM (offset convs of k=1 layers) ------
__global__ void k_gemm_n3(const float* __restrict__ A, const float* __restrict__ Bm,
                          const float* __restrict__ bias, float* __restrict__ out) {
    __shared__ float Bs[832 * 3];
    int tid = threadIdx.x;
    for (int i = tid; i < 832 * 3; i += 256) Bs[i] = Bm[i];
    __syncthreads();
    int warp = tid >> 5, lane = tid & 31;
    int m = blockIdx.x * 8 + warp;
    const float4* aRow = reinterpret_cast<const float4*>(A + (size_t)m * 832);
    float s0 = 0.f, s1 = 0.f, s2 = 0.f;
    #pragma unroll
    for (int j = 0; j < 7; j++) {
        int q = lane + j * 32;
        if (q < 208) {
            float4 v = aRow[q];
            int k = q * 4;
            s0 = fmaf(v.x, Bs[(k+0)*3+0], s0); s1 = fmaf(v.x, Bs[(k+0)*3+1], s1); s2 = fmaf(v.x, Bs[(k+0)*3+2], s2);
            s0 = fmaf(v.y, Bs[(k+1)*3+0], s0); s1 = fmaf(v.y, Bs[(k+1)*3+1], s1); s2 = fmaf(v.y, Bs[(k+1)*3+2], s2);
            s0 = fmaf(v.z, Bs[(k+2)*3+0], s0); s1 = fmaf(v.z, Bs[(k+2)*3+1], s1); s2 = fmaf(v.z, Bs[(k+2)*3+2], s2);
            s0 = fmaf(v.w, Bs[(k+3)*3+0], s0); s1 = fmaf(v.w, Bs[(k+3)*3+1], s1); s2 = fmaf(v.w, Bs[(k+3)*3+2], s2);
        }
    }
    #pragma unroll
    for (int o = 16; o; o >>= 1) {
        s0 += __shfl_xor_sync(0xffffffffu, s0, o);
        s1 += __shfl_xor_sync(0xffffffffu, s1, o);
        s2 += __shfl_xor_sync(0xffffffffu, s2, o);
    }
    if (lane == 0) {
        out[(size_t)m * 3 + 0] = s0 + bias[0];
        out[(size_t)m * 3 + 1] = s1 + bias[1];
        out[(size_t)m * 3 + 2] = s2 + bias[2];
    }
}

// ---------------- trilinear sampling: samp[m][kk][c] --------------------------
__global__ void k_sample(const float* __restrict__ src, const float* __restrict__ off,
                         float* __restrict__ samp, int C, int k, int pad) {
    int m  = blockIdx.x;
    int kk = blockIdx.y;
    int K  = gridDim.y;
    int b = m / SPA, s = m - b * SPA;
    int t = s / (HH * WW); int rem = s - t * HH * WW;
    int h = rem / WW, w = rem - h * WW;
    int kt = kk / (k * k), kh = (kk / k) % k, kw = kk % k;
    const float* op = off + (size_t)m * 3 * K + kk * 3;
    float tc = (float)(t - pad + kt) + op[0];
    float hc = (float)(h - pad + kh) + op[1];
    float wc = (float)(w - pad + kw) + op[2];
    float tf = floorf(tc), hf = floorf(hc), wf = floorf(wc);
    float ft = tc - tf, fh = hc - hf, fw = wc - wf;
    int t0 = (int)tf, h0 = (int)hf, w0 = (int)wf;

    float wgt[8]; const float* ptr[8];
    #pragma unroll
    for (int ci = 0; ci < 8; ci++) {
        int dt = ci >> 2, dh = (ci >> 1) & 1, dw = ci & 1;
        int ti = t0 + dt, hi = h0 + dh, wi = w0 + dw;
        bool valid = (ti >= 0) && (ti < TT) && (hi >= 0) && (hi < HH) && (wi >= 0) && (wi < WW);
        float wv = (dt ? ft : 1.f - ft) * (dh ? fh : 1.f - fh) * (dw ? fw : 1.f - fw);
        wgt[ci] = valid ? wv : 0.f;
        int tic = min(max(ti, 0), TT - 1);
        int hic = min(max(hi, 0), HH - 1);
        int wic = min(max(wi, 0), WW - 1);
        ptr[ci] = src + ((size_t)b * SPA + (tic * HH + hic) * WW + wic) * C;
    }
    float* dst = samp + ((size_t)m * K + kk) * C;
    for (int c = threadIdx.x * 4; c < C; c += blockDim.x * 4) {
        float4 acc = make_float4(0.f, 0.f, 0.f, 0.f);
        #pragma unroll
        for (int ci = 0; ci < 8; ci++) {
            float4 v = *reinterpret_cast<const float4*>(ptr[ci] + c);
            acc.x = fmaf(wgt[ci], v.x, acc.x);
            acc.y = fmaf(wgt[ci], v.y, acc.y);
            acc.z = fmaf(wgt[ci], v.z, acc.z);
            acc.w = fmaf(wgt[ci], v.w, acc.w);
        }
        *reinterpret_cast<float4*>(dst + c) = acc;
    }
}

// ---------------- im2col (k=3, pad=1, integer taps) ---------------------------
__global__ void k_im2col(const float* __restrict__ src, float* __restrict__ outm, int C) {
    int m  = blockIdx.x;
    int kk = blockIdx.y;
    int K  = gridDim.y;
    int b = m / SPA, s = m - b * SPA;
    int t = s / (HH * WW); int rem = s - t * HH * WW;
    int h = rem / WW, w = rem - h * WW;
    int kt = kk / 9, kh = (kk / 3) % 3, kw = kk % 3;
    int ti = t + kt - 1, hi = h + kh - 1, wi = w + kw - 1;
    bool valid = (ti >= 0) && (ti < TT) && (hi >= 0) && (hi < HH) && (wi >= 0) && (wi < WW);
    int sidx = valid ? (ti * HH + hi) * WW + wi : 0;
    const float* sp = src + ((size_t)b * SPA + sidx) * C;
    float* dst = outm + ((size_t)m * K + kk) * C;
    for (int c = threadIdx.x * 4; c < C; c += blockDim.x * 4) {
        float4 v = valid ? *reinterpret_cast<const float4*>(sp + c)
                         : make_float4(0.f, 0.f, 0.f, 0.f);
        *reinterpret_cast<float4*>(dst + c) = v;
    }
}

// ---------------- per-channel batch stats (mean, biased var) ------------------
__global__ void k_stats(const float* __restrict__ Cm, float* __restrict__ stats, int Nn) {
    int n = blockIdx.x * 32 + threadIdx.x;
    float s = 0.f, s2 = 0.f;
    if (n < Nn) {
        for (int m = threadIdx.y; m < MTOT; m += 8) {
            float v = Cm[(size_t)m * Nn + n];
            s += v; s2 += v * v;
        }
    }
    __shared__ float sh[8][32], sh2[8][32];
    sh[threadIdx.y][threadIdx.x] = s;
    sh2[threadIdx.y][threadIdx.x] = s2;
    __syncthreads();
    if (threadIdx.y == 0 && n < Nn) {
        #pragma unroll
        for (int i = 1; i < 8; i++) { s += sh[i][threadIdx.x]; s2 += sh2[i][threadIdx.x]; }
        float mean = s / (float)MTOT;
        float var  = s2 / (float)MTOT - mean * mean;
        stats[n]       = mean;
        stats[512 + n] = var;
    }
}

// ---------------- BN + ReLU + layout write ------------------------------------
__global__ void k_bnout(const float* __restrict__ Cm, const float* __restrict__ stats,
                        const float* __restrict__ gamma, const float* __restrict__ beta,
                        float* __restrict__ outp, int Nn, int mode, int ch0) {
    size_t idx = (size_t)blockIdx.x * blockDim.x + threadIdx.x;
    size_t tot = (size_t)MTOT * Nn;
    if (idx >= tot) return;
    if (mode == 0) {
        int n = (int)(idx % Nn);
        float sc = gamma[n] * rsqrtf(stats[512 + n] + 1e-5f);
        float v  = fmaf(Cm[idx] - stats[n], sc, beta[n]);
        outp[idx] = fmaxf(v, 0.f);
    } else {
        int s = (int)(idx % SPA); size_t rest = idx / SPA;
        int n = (int)(rest % Nn); int b = (int)(rest / Nn);
        float sc = gamma[n] * rsqrtf(stats[512 + n] + 1e-5f);
        float v  = fmaf(Cm[((size_t)b * SPA + s) * Nn + n] - stats[n], sc, beta[n]);
        outp[((size_t)b * 832 + ch0 + n) * SPA + s] = fmaxf(v, 0.f);
    }
}

// ============================ host orchestration ==============================
static void run_gemm_tf(const float* A, const float* Bm, const float* bias,
                        float* C, int Nn, int Kn) {
    dim3 grid((Nn + 127) / 128, MTOT / 128);
    k_gemm_tf32<<<grid, 256>>>(A, Bm, bias, C, Nn, Kn);
}

static int sample_block(int C) { return C >= 512 ? 128 : (C >= 128 ? 64 : 32); }

static void run_k1(const float* srcT, int Cin, int Cout,
                   const float* woffT, const float* boffp, const float* wTp,
                   const float* g, const float* bt,
                   float* offb, float* samp, float* conv, float* stats,
                   float* outp, int mode, int ch0) {
    k_gemm_n3<<<MTOT / 8, 256>>>(srcT, woffT, boffp, offb);          // Cin == 832 always here
    k_sample<<<dim3(MTOT, 1), sample_block(Cin)>>>(srcT, offb, samp, Cin, 1, 0);
    run_gemm_tf(samp, wTp, nullptr, conv, Cout, Cin);
    k_stats<<<(Cout + 31) / 32, dim3(32, 8)>>>(conv, stats, Cout);
    size_t tot = (size_t)MTOT * Cout;
    k_bnout<<<(unsigned)((tot + 255) / 256), 256>>>(conv, stats, g, bt, outp, Cout, mode, ch0);
}

static void run_k3(const float* srcT, int Cin, int Cout,
                   const float* woffT, const float* boffp, const float* wTp,
                   const float* g, const float* bt,
                   float* offb, float* samp, float* conv, float* stats,
                   float* outp, int mode, int ch0) {
    int Kd = 27 * Cin;
    k_im2col<<<dim3(MTOT, 27), sample_block(Cin)>>>(srcT, samp, Cin);
    run_gemm_tf(samp, woffT, boffp, offb, 81, Kd);
    k_sample<<<dim3(MTOT, 27), sample_block(Cin)>>>(srcT, offb, samp, Cin, 3, 1);
    run_gemm_tf(samp, wTp, nullptr, conv, Cout, Kd);
    k_stats<<<(Cout + 31) / 32, dim3(32, 8)>>>(conv, stats, Cout);
    size_t tot = (size_t)MTOT * Cout;
    k_bnout<<<(unsigned)((tot + 255) / 256), 256>>>(conv, stats, g, bt, outp, Cout, mode, ch0);
}

extern "C" void kernel_launch(void* const* d_in, const int* in_sizes, int n_in,
                              void* d_out, int out_size) {
    const float* x = (const float*)d_in[0];
    const float *woff[6], *boff[6], *wcv[6], *gam[6], *bet[6];
    for (int i = 0; i < 6; i++) {
        woff[i] = (const float*)d_in[1 + 5 * i];
        boff[i] = (const float*)d_in[2 + 5 * i];
        wcv[i]  = (const float*)d_in[3 + 5 * i];
        gam[i]  = (const float*)d_in[4 + 5 * i];
        bet[i]  = (const float*)d_in[5 + 5 * i];
    }
    float *xT, *xmT, *x1a, *x2a, *samp, *conv, *offb, *stats, *wT, *woffT;
    cudaGetSymbolAddress((void**)&xT,    g_xT);
    cudaGetSymbolAddress((void**)&xmT,   g_xmT);
    cudaGetSymbolAddress((void**)&x1a,   g_x1a);
    cudaGetSymbolAddress((void**)&x2a,   g_x2a);
    cudaGetSymbolAddress((void**)&samp,  g_samp);
    cudaGetSymbolAddress((void**)&conv,  g_conv);
    cudaGetSymbolAddress((void**)&offb,  g_offb);
    cudaGetSymbolAddress((void**)&stats, g_stats);
    cudaGetSymbolAddress((void**)&wT,    g_wT);
    cudaGetSymbolAddress((void**)&woffT, g_woffT);
    float* out = (float*)d_out;

    // 1) channels-last x
    k_transpose_cl<<<dim3(SPA / 32, 832 / 32, BB), dim3(32, 8)>>>(x, xT);

    // 2) weight transposes
    const int CIN[6]  = {832, 832, 160, 832, 32, 832};
    const int COUT[6] = {256, 160, 320, 32, 128, 128};
    const int KK[6]   = {1, 1, 27, 1, 27, 1};
    size_t wtoff[6], wooff[6];
    {
        size_t a = 0, bsz = 0;
        for (int i = 0; i < 6; i++) { wtoff[i] = a; a += (size_t)KK[i] * CIN[i] * COUT[i]; }
        for (int i = 0; i < 6; i++) { wooff[i] = bsz; bsz += (size_t)KK[i] * CIN[i] * (3 * KK[i]); }
    }
    for (int i = 0; i < 6; i++) {
        int tot1 = KK[i] * CIN[i] * COUT[i];
        k_wtrans<<<(tot1 + 255) / 256, 256>>>(wcv[i], wT + wtoff[i], COUT[i], CIN[i], KK[i]);
        int tot2 = KK[i] * CIN[i] * 3 * KK[i];
        k_wtrans<<<(tot2 + 255) / 256, 256>>>(woff[i], woffT + wooff[i], 3 * KK[i], CIN[i], KK[i]);
    }

    // 3) branch 0: deform(x, 832->256, k=1) -> out channels [0,256)
    run_k1(xT, 832, 256, woffT + wooff[0], boff[0], wT + wtoff[0], gam[0], bet[0],
           offb, samp, conv, stats, out, 1, 0);

    // 4) branch 1: deform(x, 832->160, k=1) -> x1a ; deform(x1a, 160->320, k=3) -> [256,576)
    run_k1(xT, 832, 160, woffT + wooff[1], boff[1], wT + wtoff[1], gam[1], bet[1],
           offb, samp, conv, stats, x1a, 0, 0);
    run_k3(x1a, 160, 320, woffT + wooff[2], boff[2], wT + wtoff[2], gam[2], bet[2],
           offb, samp, conv, stats, out, 1, 256);

    // 5) branch 2: deform(x, 832->32, k=1) -> x2a ; deform(x2a, 32->128, k=3) -> [576,704)
    run_k1(xT, 832, 32, woffT + wooff[3], boff[3], wT + wtoff[3], gam[3], bet[3],
           offb, samp, conv, stats, x2a, 0, 0);
    run_k3(x2a, 32, 128, woffT + wooff[4], boff[4], wT + wtoff[4], gam[4], bet[4],
           offb, samp, conv, stats, out, 1, 576);

    // 6) branch 3: separable maxpool -> deform(xm, 832->128, k=1) -> [704,832)
    {
        float* tmp1 = samp;
        float* tmp2 = samp + (size_t)MTOT * 832;
        int nthr = (int)(((size_t)MTOT * 208 + 255) / 256);
        k_max3<<<nthr, 256>>>(xT,   tmp1, 1,       WW);
        k_max3<<<nthr, 256>>>(tmp1, tmp2, WW,      HH);
        k_max3<<<nthr, 256>>>(tmp2, xmT,  HH * WW, TT);
    }
    run_k1(xmT, 832, 128, woffT + wooff[5], boff[5], wT + wtoff[5], gam[5], bet[5],
           offb, samp, conv, stats, out, 1, 704);
}

// round 5
// speedup vs baseline: 1.9171x; 1.2419x over previous
#include <cuda_runtime.h>
#include <math.h>
#include <stdint.h>

// Problem constants
#define BB   8
#define TT   8
#define HH   14
#define WW   14
#define SPA  1568          // T*H*W
#define MTOT 12544         // B*SPA
#define KC   32            // GEMM k-chunk

// ---------------- scratch (device globals; no allocation allowed) -------------
__device__ float g_xT [(size_t)MTOT * 832];   // x channels-last
__device__ float g_xmT[(size_t)MTOT * 832];   // maxpool(x) channels-last
__device__ float g_x1a[(size_t)MTOT * 160];   // branch1 intermediate
__device__ float g_x2a[(size_t)MTOT * 32];    // branch2 intermediate
__device__ float g_samp[(size_t)MTOT * 4320]; // im2col / sampled rows (max layer2)
__device__ float g_conv[(size_t)MTOT * 320];  // raw conv output (max layer2)
__device__ float g_offb[(size_t)MTOT * 96];   // offset field (stride 96 for k=3)
__device__ float g_stats[1024];               // [0..511]=mean, [512..1023]=var
__device__ float g_wT  [1972224];             // transposed main-conv weights
__device__ float g_woffT[520000];             // transposed offset-conv weights

__device__ __forceinline__ uint32_t f2tf(float x) {
    uint32_t u; asm("cvt.rna.tf32.f32 %0, %1;" : "=r"(u) : "f"(x)); return u;
}

__device__ __forceinline__ void cpa16(uint32_t dst, const void* src, int szBytes) {
    asm volatile("cp.async.cg.shared.global [%0], [%1], 16, %2;"
                 :: "r"(dst), "l"(src), "r"(szBytes));
}

// ---------------- transpose x: [B,C,SPA] -> [B,SPA,C] (C=832) -----------------
__global__ void k_transpose_cl(const float* __restrict__ in, float* __restrict__ out) {
    __shared__ float tile[32][33];
    int b  = blockIdx.z;
    int s0 = blockIdx.x * 32;
    int c0 = blockIdx.y * 32;
    int tx = threadIdx.x, ty = threadIdx.y;
    #pragma unroll
    for (int i = ty; i < 32; i += 8)
        tile[i][tx] = in[((size_t)b * 832 + (c0 + i)) * SPA + s0 + tx];
    __syncthreads();
    #pragma unroll
    for (int i = ty; i < 32; i += 8)
        out[((size_t)b * SPA + (s0 + i)) * 832 + c0 + tx] = tile[tx][i];
}

// ---------------- separable 3-max along one dim, channels-last ----------------
__global__ void k_max3(const float* __restrict__ in, float* __restrict__ out,
                       int ddiv, int dmod) {
    size_t idx = (size_t)blockIdx.x * blockDim.x + threadIdx.x;
    if (idx >= (size_t)MTOT * 208) return;
    int c4 = (int)(idx % 208);
    size_t m = idx / 208;
    int s = (int)(m % SPA);
    int coord = (s / ddiv) % dmod;
    const float4* p = reinterpret_cast<const float4*>(in) + m * 208 + c4;
    float4 v = *p;
    if (coord > 0) {
        float4 u = *(p - (size_t)ddiv * 208);
        v.x = fmaxf(v.x, u.x); v.y = fmaxf(v.y, u.y);
        v.z = fmaxf(v.z, u.z); v.w = fmaxf(v.w, u.w);
    }
    if (coord < dmod - 1) {
        float4 u = *(p + (size_t)ddiv * 208);
        v.x = fmaxf(v.x, u.x); v.y = fmaxf(v.y, u.y);
        v.z = fmaxf(v.z, u.z); v.w = fmaxf(v.w, u.w);
    }
    reinterpret_cast<float4*>(out)[m * 208 + c4] = v;
}

// ---------------- weight transpose: w[Cout,Cin,K] -> wT[(k*Cin+c)*Cout+oc] ----
__global__ void k_wtrans(const float* __restrict__ w, float* __restrict__ wT,
                         int Cout, int Cin, int K) {
    int idx = blockIdx.x * blockDim.x + threadIdx.x;
    int tot = Cout * Cin * K;
    if (idx >= tot) return;
    int oc = idx % Cout; int rest = idx / Cout;
    int c  = rest % Cin; int kk = rest / Cin;
    wT[idx] = w[((size_t)oc * Cin + c) * K + kk];
}

// padded variant: output stride CoutPad, zero-filled beyond Cout
__global__ void k_wtrans_pad(const float* __restrict__ w, float* __restrict__ wT,
                             int Cout, int CoutPad, int Cin, int K) {
    int idx = blockIdx.x * blockDim.x + threadIdx.x;
    int tot = CoutPad * Cin * K;
    if (idx >= tot) return;
    int oc = idx % CoutPad; int rest = idx / CoutPad;
    int c  = rest % Cin; int kk = rest / Cin;
    wT[idx] = (oc < Cout) ? w[((size_t)oc * Cin + c) * K + kk] : 0.f;
}

// ---------------- pipelined tf32 GEMM: C[M,N] = A[M,K] @ B[K,N] (+bias) -------
// M mult of 128, K mult of 32, N mult of 32 (guarded per 128-block).
// 2-stage cp.async double buffering; smem fp32, tf32 convert at fragment load.
// smem: As[2][128][36] + Bs[2][32][132] floats (70,656 B dynamic).
#define AS(st, m, k) sm[(size_t)(st) * (128 * 36) + (m) * 36 + (k)]
#define BS(st, k, n) sm[(size_t)(2 * 128 * 36) + (st) * (32 * 132) + (k) * 132 + (n)]

__global__ __launch_bounds__(256) void k_gemm_pipe(
    const float* __restrict__ A, const float* __restrict__ Bm,
    const float* __restrict__ bias, int nBias,
    float* __restrict__ Cc, int Nn, int Kn)
{
    extern __shared__ float sm[];
    int tid = threadIdx.x;
    int lane = tid & 31, warp = tid >> 5;
    int warpM = warp & 1, warpN = warp >> 1;
    int m0 = blockIdx.y * 128, n0 = blockIdx.x * 128;
    int g = lane >> 2, tg = lane & 3;

    float acc[4][4][4];
    #pragma unroll
    for (int i = 0; i < 4; i++)
        #pragma unroll
        for (int j = 0; j < 4; j++)
            #pragma unroll
            for (int q = 0; q < 4; q++) acc[i][j][q] = 0.f;

    // A load mapping: 2 threads/row, each 4x float4 (16 cols)
    const int aRowT = tid >> 1;
    const int aCol0 = (tid & 1) * 16;
    const float* aPtr = A + (size_t)(m0 + aRowT) * Kn + aCol0;
    // B load mapping: 8 threads/row, each 4x float4 spaced by 32 cols
    const int bRowT = tid >> 3;
    const int bCol0 = (tid & 7) * 4;

    uint32_t aBase = (uint32_t)__cvta_generic_to_shared(&AS(0, aRowT, aCol0));
    uint32_t bBase = (uint32_t)__cvta_generic_to_shared(&BS(0, bRowT, bCol0));
    const uint32_t aStage = 128 * 36 * 4;
    const uint32_t bStage = 32 * 132 * 4;

    int nChunks = Kn / KC;

    // preload chunk 0 into stage 0
    {
        #pragma unroll
        for (int j = 0; j < 4; j++)
            cpa16(aBase + j * 16, aPtr + j * 4, 16);
        const float* bp = Bm + (size_t)bRowT * Nn;
        #pragma unroll
        for (int j = 0; j < 4; j++) {
            int col = bCol0 + j * 32;
            int sz = (n0 + col < Nn) ? 16 : 0;
            cpa16(bBase + j * 32 * 4, bp + n0 + col, sz);
        }
        asm volatile("cp.async.commit_group;");
    }

    for (int c = 0; c < nChunks; c++) {
        int st = c & 1;
        if (c + 1 < nChunks) {
            int k1 = (c + 1) * KC;
            int s2 = (c + 1) & 1;
            #pragma unroll
            for (int j = 0; j < 4; j++)
                cpa16(aBase + s2 * aStage + j * 16, aPtr + k1 + j * 4, 16);
            const float* bp = Bm + (size_t)(k1 + bRowT) * Nn;
            #pragma unroll
            for (int j = 0; j < 4; j++) {
                int col = bCol0 + j * 32;
                int sz = (n0 + col < Nn) ? 16 : 0;
                cpa16(bBase + s2 * bStage + j * 32 * 4, bp + n0 + col, sz);
            }
            asm volatile("cp.async.commit_group;");
            asm volatile("cp.async.wait_group 1;");
        } else {
            asm volatile("cp.async.wait_group 0;");
        }
        __syncthreads();

        #pragma unroll
        for (int ks = 0; ks < 4; ks++) {
            uint32_t af[4][4], bf[4][2];
            #pragma unroll
            for (int mt = 0; mt < 4; mt++) {
                int mr = warpM * 64 + mt * 16 + g;
                af[mt][0] = f2tf(AS(st, mr,     ks * 8 + tg));
                af[mt][1] = f2tf(AS(st, mr + 8, ks * 8 + tg));
                af[mt][2] = f2tf(AS(st, mr,     ks * 8 + tg + 4));
                af[mt][3] = f2tf(AS(st, mr + 8, ks * 8 + tg + 4));
            }
            #pragma unroll
            for (int nt = 0; nt < 4; nt++) {
                int nc = warpN * 32 + nt * 8 + g;
                bf[nt][0] = f2tf(BS(st, ks * 8 + tg,     nc));
                bf[nt][1] = f2tf(BS(st, ks * 8 + tg + 4, nc));
            }
            #pragma unroll
            for (int mt = 0; mt < 4; mt++)
                #pragma unroll
                for (int nt = 0; nt < 4; nt++)
                    asm volatile(
                        "mma.sync.aligned.m16n8k8.row.col.f32.tf32.tf32.f32 "
                        "{%0,%1,%2,%3}, {%4,%5,%6,%7}, {%8,%9}, {%0,%1,%2,%3};"
                        : "+f"(acc[mt][nt][0]), "+f"(acc[mt][nt][1]),
                          "+f"(acc[mt][nt][2]), "+f"(acc[mt][nt][3])
                        : "r"(af[mt][0]), "r"(af[mt][1]), "r"(af[mt][2]), "r"(af[mt][3]),
                          "r"(bf[nt][0]), "r"(bf[nt][1]));
        }
        __syncthreads();
    }

    // epilogue
    #pragma unroll
    for (int mt = 0; mt < 4; mt++) {
        int r0 = m0 + warpM * 64 + mt * 16 + g;
        #pragma unroll
        for (int nt = 0; nt < 4; nt++) {
            int c0 = n0 + warpN * 32 + nt * 8 + tg * 2;
            if (c0 < Nn) {
                float b0 = (bias && c0 < nBias) ? bias[c0] : 0.f;
                float b1 = (bias && c0 + 1 < nBias) ? bias[c0 + 1] : 0.f;
                Cc[(size_t)r0 * Nn + c0]           = acc[mt][nt][0] + b0;
                Cc[(size_t)r0 * Nn + c0 + 1]       = acc[mt][nt][1] + b1;
                Cc[(size_t)(r0 + 8) * Nn + c0]     = acc[mt][nt][2] + b0;
                Cc[(size_t)(r0 + 8) * Nn + c0 + 1] = acc[mt][nt][3] + b1;
            }
        }
    }
}

// ---------------- dedicated N=3, K=832 GEMM (offset convs of k=1 layers) ------
__global__ void k_gemm_n3(const float* __restrict__ A, const float* __restrict__ Bm,
                          const float* __restrict__ bias, float* __restrict__ out) {
    __shared__ float Bs[832 * 3];
    int tid = threadIdx.x;
    for (int i = tid; i < 832 * 3; i += 256) Bs[i] = Bm[i];
    __syncthreads();
    int warp = tid >> 5, lane = tid & 31;
    int m = blockIdx.x * 8 + warp;
    const float4* aRow = reinterpret_cast<const float4*>(A + (size_t)m * 832);
    float s0 = 0.f, s1 = 0.f, s2 = 0.f;
    #pragma unroll
    for (int j = 0; j < 7; j++) {
        int q = lane + j * 32;
        if (q < 208) {
            float4 v = aRow[q];
            int k = q * 4;
            s0 = fmaf(v.x, Bs[(k+0)*3+0], s0); s1 = fmaf(v.x, Bs[(k+0)*3+1], s1); s2 = fmaf(v.x, Bs[(k+0)*3+2], s2);
            s0 = fmaf(v.y, Bs[(k+1)*3+0], s0); s1 = fmaf(v.y, Bs[(k+1)*3+1], s1); s2 = fmaf(v.y, Bs[(k+1)*3+2], s2);
            s0 = fmaf(v.z, Bs[(k+2)*3+0], s0); s1 = fmaf(v.z, Bs[(k+2)*3+1], s1); s2 = fmaf(v.z, Bs[(k+2)*3+2], s2);
            s0 = fmaf(v.w, Bs[(k+3)*3+0], s0); s1 = fmaf(v.w, Bs[(k+3)*3+1], s1); s2 = fmaf(v.w, Bs[(k+3)*3+2], s2);
        }
    }
    #pragma unroll
    for (int o = 16; o; o >>= 1) {
        s0 += __shfl_xor_sync(0xffffffffu, s0, o);
        s1 += __shfl_xor_sync(0xffffffffu, s1, o);
        s2 += __shfl_xor_sync(0xffffffffu, s2, o);
    }
    if (lane == 0) {
        out[(size_t)m * 3 + 0] = s0 + bias[0];
        out[(size_t)m * 3 + 1] = s1 + bias[1];
        out[(size_t)m * 3 + 2] = s2 + bias[2];
    }
}

// ---------------- trilinear sampling: samp[m][kk][c] --------------------------
__global__ void k_sample(const float* __restrict__ src, const float* __restrict__ off,
                         float* __restrict__ samp, int C, int k, int pad, int offStride) {
    int m  = blockIdx.x;
    int kk = blockIdx.y;
    int K  = gridDim.y;
    int b = m / SPA, s = m - b * SPA;
    int t = s / (HH * WW); int rem = s - t * HH * WW;
    int h = rem / WW, w = rem - h * WW;
    int kt = kk / (k * k), kh = (kk / k) % k, kw = kk % k;
    const float* op = off + (size_t)m * offStride + kk * 3;
    float tc = (float)(t - pad + kt) + op[0];
    float hc = (float)(h - pad + kh) + op[1];
    float wc = (float)(w - pad + kw) + op[2];
    float tf = floorf(tc), hf = floorf(hc), wf = floorf(wc);
    float ft = tc - tf, fh = hc - hf, fw = wc - wf;
    int t0 = (int)tf, h0 = (int)hf, w0 = (int)wf;

    float wgt[8]; const float* ptr[8];
    #pragma unroll
    for (int ci = 0; ci < 8; ci++) {
        int dt = ci >> 2, dh = (ci >> 1) & 1, dw = ci & 1;
        int ti = t0 + dt, hi = h0 + dh, wi = w0 + dw;
        bool valid = (ti >= 0) && (ti < TT) && (hi >= 0) && (hi < HH) && (wi >= 0) && (wi < WW);
        float wv = (dt ? ft : 1.f - ft) * (dh ? fh : 1.f - fh) * (dw ? fw : 1.f - fw);
        wgt[ci] = valid ? wv : 0.f;
        int tic = min(max(ti, 0), TT - 1);
        int hic = min(max(hi, 0), HH - 1);
        int wic = min(max(wi, 0), WW - 1);
        ptr[ci] = src + ((size_t)b * SPA + (tic * HH + hic) * WW + wic) * C;
    }
    float* dst = samp + ((size_t)m * K + kk) * C;
    for (int c = threadIdx.x * 4; c < C; c += blockDim.x * 4) {
        float4 acc = make_float4(0.f, 0.f, 0.f, 0.f);
        #pragma unroll
        for (int ci = 0; ci < 8; ci++) {
            float4 v = *reinterpret_cast<const float4*>(ptr[ci] + c);
            acc.x = fmaf(wgt[ci], v.x, acc.x);
            acc.y = fmaf(wgt[ci], v.y, acc.y);
            acc.z = fmaf(wgt[ci], v.z, acc.z);
            acc.w = fmaf(wgt[ci], v.w, acc.w);
        }
        *reinterpret_cast<float4*>(dst + c) = acc;
    }
}

// ---------------- im2col (k=3, pad=1, integer taps) ---------------------------
__global__ void k_im2col(const float* __restrict__ src, float* __restrict__ outm, int C) {
    int m  = blockIdx.x;
    int kk = blockIdx.y;
    int K  = gridDim.y;
    int b = m / SPA, s = m - b * SPA;
    int t = s / (HH * WW); int rem = s - t * HH * WW;
    int h = rem / WW, w = rem - h * WW;
    int kt = kk / 9, kh = (kk / 3) % 3, kw = kk % 3;
    int ti = t + kt - 1, hi = h + kh - 1, wi = w + kw - 1;
    bool valid = (ti >= 0) && (ti < TT) && (hi >= 0) && (hi < HH) && (wi >= 0) && (wi < WW);
    int sidx = valid ? (ti * HH + hi) * WW + wi : 0;
    const float* sp = src + ((size_t)b * SPA + sidx) * C;
    float* dst = outm + ((size_t)m * K + kk) * C;
    for (int c = threadIdx.x * 4; c < C; c += blockDim.x * 4) {
        float4 v = valid ? *reinterpret_cast<const float4*>(sp + c)
                         : make_float4(0.f, 0.f, 0.f, 0.f);
        *reinterpret_cast<float4*>(dst + c) = v;
    }
}

// ---------------- per-channel batch stats (mean, biased var) ------------------
__global__ void k_stats(const float* __restrict__ Cm, float* __restrict__ stats, int Nn) {
    int n = blockIdx.x * 32 + threadIdx.x;
    float s = 0.f, s2 = 0.f;
    if (n < Nn) {
        for (int m = threadIdx.y; m < MTOT; m += 8) {
            float v = Cm[(size_t)m * Nn + n];
            s += v; s2 += v * v;
        }
    }
    __shared__ float sh[8][32], sh2[8][32];
    sh[threadIdx.y][threadIdx.x] = s;
    sh2[threadIdx.y][threadIdx.x] = s2;
    __syncthreads();
    if (threadIdx.y == 0 && n < Nn) {
        #pragma unroll
        for (int i = 1; i < 8; i++) { s += sh[i][threadIdx.x]; s2 += sh2[i][threadIdx.x]; }
        float mean = s / (float)MTOT;
        float var  = s2 / (float)MTOT - mean * mean;
        stats[n]       = mean;
        stats[512 + n] = var;
    }
}

// ---------------- BN + ReLU + layout write ------------------------------------
__global__ void k_bnout(const float* __restrict__ Cm, const float* __restrict__ stats,
                        const float* __restrict__ gamma, const float* __restrict__ beta,
                        float* __restrict__ outp, int Nn, int mode, int ch0) {
    size_t idx = (size_t)blockIdx.x * blockDim.x + threadIdx.x;
    size_t tot = (size_t)MTOT * Nn;
    if (idx >= tot) return;
    if (mode == 0) {
        int n = (int)(idx % Nn);
        float sc = gamma[n] * rsqrtf(stats[512 + n] + 1e-5f);
        float v  = fmaf(Cm[idx] - stats[n], sc, beta[n]);
        outp[idx] = fmaxf(v, 0.f);
    } else {
        int s = (int)(idx % SPA); size_t rest = idx / SPA;
        int n = (int)(rest % Nn); int b = (int)(rest / Nn);
        float sc = gamma[n] * rsqrtf(stats[512 + n] + 1e-5f);
        float v  = fmaf(Cm[((size_t)b * SPA + s) * Nn + n] - stats[n], sc, beta[n]);
        outp[((size_t)b * 832 + ch0 + n) * SPA + s] = fmaxf(v, 0.f);
    }
}

// ============================ host orchestration ==============================
static const int GEMM_SMEM = (2 * 128 * 36 + 2 * 32 * 132) * 4;  // 70,656 B

static void run_gemm_pipe(const float* A, const float* Bm, const float* bias, int nBias,
                          float* C, int Nn, int Kn) {
    cudaFuncSetAttribute(k_gemm_pipe, cudaFuncAttributeMaxDynamicSharedMemorySize, GEMM_SMEM);
    dim3 grid((Nn + 127) / 128, MTOT / 128);
    k_gemm_pipe<<<grid, 256, GEMM_SMEM>>>(A, Bm, bias, nBias, C, Nn, Kn);
}

static int sample_block(int C) { return C >= 512 ? 128 : (C >= 128 ? 64 : 32); }

static void run_k1(const float* srcT, int Cin, int Cout,
                   const float* woffT, const float* boffp, const float* wTp,
                   const float* g, const float* bt,
                   float* offb, float* samp, float* conv, float* stats,
                   float* outp, int mode, int ch0) {
    k_gemm_n3<<<MTOT / 8, 256>>>(srcT, woffT, boffp, offb);          // Cin == 832 always here
    k_sample<<<dim3(MTOT, 1), sample_block(Cin)>>>(srcT, offb, samp, Cin, 1, 0, 3);
    run_gemm_pipe(samp, wTp, nullptr, 0, conv, Cout, Cin);
    k_stats<<<(Cout + 31) / 32, dim3(32, 8)>>>(conv, stats, Cout);
    size_t tot = (size_t)MTOT * Cout;
    k_bnout<<<(unsigned)((tot + 255) / 256), 256>>>(conv, stats, g, bt, outp, Cout, mode, ch0);
}

static void run_k3(const float* srcT, int Cin, int Cout,
                   const float* woffT, const float* boffp, const float* wTp,
                   const float* g, const float* bt,
                   float* offb, float* samp, float* conv, float* stats,
                   float* outp, int mode, int ch0) {
    int Kd = 27 * Cin;
    k_im2col<<<dim3(MTOT, 27), sample_block(Cin)>>>(srcT, samp, Cin);
    run_gemm_pipe(samp, woffT, boffp, 81, offb, 96, Kd);   // offsets padded N=96
    k_sample<<<dim3(MTOT, 27), sample_block(Cin)>>>(srcT, offb, samp, Cin, 3, 1, 96);
    run_gemm_pipe(samp, wTp, nullptr, 0, conv, Cout, Kd);
    k_stats<<<(Cout + 31) / 32, dim3(32, 8)>>>(conv, stats, Cout);
    size_t tot = (size_t)MTOT * Cout;
    k_bnout<<<(unsigned)((tot + 255) / 256), 256>>>(conv, stats, g, bt, outp, Cout, mode, ch0);
}

extern "C" void kernel_launch(void* const* d_in, const int* in_sizes, int n_in,
                              void* d_out, int out_size) {
    const float* x = (const float*)d_in[0];
    const float *woff[6], *boff[6], *wcv[6], *gam[6], *bet[6];
    for (int i = 0; i < 6; i++) {
        woff[i] = (const float*)d_in[1 + 5 * i];
        boff[i] = (const float*)d_in[2 + 5 * i];
        wcv[i]  = (const float*)d_in[3 + 5 * i];
        gam[i]  = (const float*)d_in[4 + 5 * i];
        bet[i]  = (const float*)d_in[5 + 5 * i];
    }
    float *xT, *xmT, *x1a, *x2a, *samp, *conv, *offb, *stats, *wT, *woffT;
    cudaGetSymbolAddress((void**)&xT,    g_xT);
    cudaGetSymbolAddress((void**)&xmT,   g_xmT);
    cudaGetSymbolAddress((void**)&x1a,   g_x1a);
    cudaGetSymbolAddress((void**)&x2a,   g_x2a);
    cudaGetSymbolAddress((void**)&samp,  g_samp);
    cudaGetSymbolAddress((void**)&conv,  g_conv);
    cudaGetSymbolAddress((void**)&offb,  g_offb);
    cudaGetSymbolAddress((void**)&stats, g_stats);
    cudaGetSymbolAddress((void**)&wT,    g_wT);
    cudaGetSymbolAddress((void**)&woffT, g_woffT);
    float* out = (float*)d_out;

    // 1) channels-last x
    k_transpose_cl<<<dim3(SPA / 32, 832 / 32, BB), dim3(32, 8)>>>(x, xT);

    // 2) weight transposes
    const int CIN[6]  = {832, 832, 160, 832, 32, 832};
    const int COUT[6] = {256, 160, 320, 32, 128, 128};
    const int KK[6]   = {1, 1, 27, 1, 27, 1};
    size_t wtoff[6], wooff[6];
    {
        size_t a = 0, bsz = 0;
        for (int i = 0; i < 6; i++) { wtoff[i] = a; a += (size_t)KK[i] * CIN[i] * COUT[i]; }
        for (int i = 0; i < 6; i++) {
            wooff[i] = bsz;
            bsz += (KK[i] == 1) ? (size_t)CIN[i] * 3 : (size_t)KK[i] * CIN[i] * 96;
        }
    }
    for (int i = 0; i < 6; i++) {
        int tot1 = KK[i] * CIN[i] * COUT[i];
        k_wtrans<<<(tot1 + 255) / 256, 256>>>(wcv[i], wT + wtoff[i], COUT[i], CIN[i], KK[i]);
        if (KK[i] == 1) {
            int tot2 = CIN[i] * 3;
            k_wtrans<<<(tot2 + 255) / 256, 256>>>(woff[i], woffT + wooff[i], 3, CIN[i], 1);
        } else {
            int tot2 = KK[i] * CIN[i] * 96;
            k_wtrans_pad<<<(tot2 + 255) / 256, 256>>>(woff[i], woffT + wooff[i],
                                                      81, 96, CIN[i], KK[i]);
        }
    }

    // 3) branch 0: deform(x, 832->256, k=1) -> out channels [0,256)
    run_k1(xT, 832, 256, woffT + wooff[0], boff[0], wT + wtoff[0], gam[0], bet[0],
           offb, samp, conv, stats, out, 1, 0);

    // 4) branch 1: deform(x, 832->160, k=1) -> x1a ; deform(x1a, 160->320, k=3) -> [256,576)
    run_k1(xT, 832, 160, woffT + wooff[1], boff[1], wT + wtoff[1], gam[1], bet[1],
           offb, samp, conv, stats, x1a, 0, 0);
    run_k3(x1a, 160, 320, woffT + wooff[2], boff[2], wT + wtoff[2], gam[2], bet[2],
           offb, samp, conv, stats, out, 1, 256);

    // 5) branch 2: deform(x, 832->32, k=1) -> x2a ; deform(x2a, 32->128, k=3) -> [576,704)
    run_k1(xT, 832, 32, woffT + wooff[3], boff[3], wT + wtoff[3], gam[3], bet[3],
           offb, samp, conv, stats, x2a, 0, 0);
    run_k3(x2a, 32, 128, woffT + wooff[4], boff[4], wT + wtoff[4], gam[4], bet[4],
           offb, samp, conv, stats, out, 1, 576);

    // 6) branch 3: separable maxpool -> deform(xm, 832->128, k=1) -> [704,832)
    {
        float* tmp1 = samp;
        float* tmp2 = samp + (size_t)MTOT * 832;
        int nthr = (int)(((size_t)MTOT * 208 + 255) / 256);
        k_max3<<<nthr, 256>>>(xT,   tmp1, 1,       WW);
        k_max3<<<nthr, 256>>>(tmp1, tmp2, WW,      HH);
        k_max3<<<nthr, 256>>>(tmp2, xmT,  HH * WW, TT);
    }
    run_k1(xmT, 832, 128, woffT + wooff[5], boff[5], wT + wtoff[5], gam[5], bet[5],
           offb, samp, conv, stats, out, 1, 704);
}

// round 6
// speedup vs baseline: 1.9740x; 1.0297x over previous
#include <cuda_runtime.h>
#include <math.h>
#include <stdint.h>

// Problem constants
#define BB   8
#define TT   8
#define HH   14
#define WW   14
#define SPA  1568          // T*H*W
#define MTOT 12544         // B*SPA
#define KC   32            // GEMM k-chunk

// ---------------- scratch (device globals; no allocation allowed) -------------
__device__ float g_xT [(size_t)MTOT * 832];   // x channels-last
__device__ float g_xmT[(size_t)MTOT * 832];   // maxpool(x) channels-last
__device__ float g_x1a[(size_t)MTOT * 160];   // branch1 intermediate
__device__ float g_x2a[(size_t)MTOT * 32];    // branch2 intermediate
__device__ float g_samp[(size_t)MTOT * 4320]; // im2col / sampled rows (tf32 bits)
__device__ float g_conv[(size_t)MTOT * 320];  // raw conv output (max layer2)
__device__ float g_offb[(size_t)MTOT * 96];   // offset field (stride 96 for k=3)
__device__ float g_stats[1024];               // [0..511]=mean, [512..1023]=var
__device__ float g_wT  [1972224];             // transposed main-conv weights (tf32)
__device__ float g_woffT[520000];             // transposed offset-conv weights

__device__ __forceinline__ uint32_t f2tf(float x) {
    uint32_t u; asm("cvt.rna.tf32.f32 %0, %1;" : "=r"(u) : "f"(x)); return u;
}
__device__ __forceinline__ float f2tff(float x) { return __uint_as_float(f2tf(x)); }

__device__ __forceinline__ void cpa16(uint32_t dst, const void* src, int szBytes) {
    asm volatile("cp.async.cg.shared.global [%0], [%1], 16, %2;"
                 :: "r"(dst), "l"(src), "r"(szBytes));
}

// ---------------- transpose x: [B,C,SPA] -> [B,SPA,C] (C=832) -----------------
__global__ void k_transpose_cl(const float* __restrict__ in, float* __restrict__ out) {
    __shared__ float tile[32][33];
    int b  = blockIdx.z;
    int s0 = blockIdx.x * 32;
    int c0 = blockIdx.y * 32;
    int tx = threadIdx.x, ty = threadIdx.y;
    #pragma unroll
    for (int i = ty; i < 32; i += 8)
        tile[i][tx] = in[((size_t)b * 832 + (c0 + i)) * SPA + s0 + tx];
    __syncthreads();
    #pragma unroll
    for (int i = ty; i < 32; i += 8)
        out[((size_t)b * SPA + (s0 + i)) * 832 + c0 + tx] = tile[tx][i];
}

// ---------------- separable 3-max along one dim, channels-last ----------------
__global__ void k_max3(const float* __restrict__ in, float* __restrict__ out,
                       int ddiv, int dmod) {
    size_t idx = (size_t)blockIdx.x * blockDim.x + threadIdx.x;
    if (idx >= (size_t)MTOT * 208) return;
    int c4 = (int)(idx % 208);
    size_t m = idx / 208;
    int s = (int)(m % SPA);
    int coord = (s / ddiv) % dmod;
    const float4* p = reinterpret_cast<const float4*>(in) + m * 208 + c4;
    float4 v = *p;
    if (coord > 0) {
        float4 u = *(p - (size_t)ddiv * 208);
        v.x = fmaxf(v.x, u.x); v.y = fmaxf(v.y, u.y);
        v.z = fmaxf(v.z, u.z); v.w = fmaxf(v.w, u.w);
    }
    if (coord < dmod - 1) {
        float4 u = *(p + (size_t)ddiv * 208);
        v.x = fmaxf(v.x, u.x); v.y = fmaxf(v.y, u.y);
        v.z = fmaxf(v.z, u.z); v.w = fmaxf(v.w, u.w);
    }
    reinterpret_cast<float4*>(out)[m * 208 + c4] = v;
}

// ---------------- fused weight transpose: all 12 jobs in one launch -----------
// dst[(kk*Cin + c)*CoutPad + oc] = (oc < Cout ? src[(oc*Cin + c)*K + kk] : 0)
struct WJobs {
    const float* src[12];
    float*       dst[12];
    int cout[12], coutpad[12], cin[12], kk[12], cvt[12];
    int start[13];
};

__global__ void k_wtrans_all(WJobs jb) {
    int idx = blockIdx.x * blockDim.x + threadIdx.x;
    if (idx >= jb.start[12]) return;
    int j = 0;
    #pragma unroll
    for (int i = 1; i < 12; i++) if (idx >= jb.start[i]) j = i;
    int local = idx - jb.start[j];
    int cp = jb.coutpad[j], ci = jb.cin[j], K = jb.kk[j];
    int oc = local % cp; int rest = local / cp;
    int c  = rest % ci;  int kk = rest / ci;
    float v = (oc < jb.cout[j]) ? jb.src[j][((size_t)oc * ci + c) * K + kk] : 0.f;
    if (jb.cvt[j]) v = __uint_as_float(f2tf(v));
    jb.dst[j][local] = v;
}

// ---------------- pipelined tf32 GEMM: C[M,N] = A[M,K] @ B[K,N] (+bias) -------
// A and B are PRE-CONVERTED to tf32 bit patterns by producers. No cvt here.
// M mult of 128, K mult of 32, N mult of 32 (guarded per 128-block).
#define AS(st, m, k) sm[(size_t)(st) * (128 * 36) + (m) * 36 + (k)]
#define BS(st, k, n) sm[(size_t)(2 * 128 * 36) + (st) * (32 * 132) + (k) * 132 + (n)]

__global__ __launch_bounds__(256) void k_gemm_pipe(
    const float* __restrict__ A, const float* __restrict__ Bm,
    const float* __restrict__ bias, int nBias,
    float* __restrict__ Cc, int Nn, int Kn)
{
    extern __shared__ float sm[];
    int tid = threadIdx.x;
    int lane = tid & 31, warp = tid >> 5;
    int warpM = warp & 1, warpN = warp >> 1;
    int m0 = blockIdx.y * 128, n0 = blockIdx.x * 128;
    int g = lane >> 2, tg = lane & 3;

    float acc[4][4][4];
    #pragma unroll
    for (int i = 0; i < 4; i++)
        #pragma unroll
        for (int j = 0; j < 4; j++)
            #pragma unroll
            for (int q = 0; q < 4; q++) acc[i][j][q] = 0.f;

    const int aRowT = tid >> 1;
    const int aCol0 = (tid & 1) * 16;
    const float* aPtr = A + (size_t)(m0 + aRowT) * Kn + aCol0;
    const int bRowT = tid >> 3;
    const int bCol0 = (tid & 7) * 4;

    uint32_t aBase = (uint32_t)__cvta_generic_to_shared(&AS(0, aRowT, aCol0));
    uint32_t bBase = (uint32_t)__cvta_generic_to_shared(&BS(0, bRowT, bCol0));
    const uint32_t aStage = 128 * 36 * 4;
    const uint32_t bStage = 32 * 132 * 4;

    int nChunks = Kn / KC;

    {
        #pragma unroll
        for (int j = 0; j < 4; j++)
            cpa16(aBase + j * 16, aPtr + j * 4, 16);
        const float* bp = Bm + (size_t)bRowT * Nn;
        #pragma unroll
        for (int j = 0; j < 4; j++) {
            int col = bCol0 + j * 32;
            int sz = (n0 + col < Nn) ? 16 : 0;
            cpa16(bBase + j * 32 * 4, bp + n0 + col, sz);
        }
        asm volatile("cp.async.commit_group;");
    }

    for (int c = 0; c < nChunks; c++) {
        int st = c & 1;
        if (c + 1 < nChunks) {
            int k1 = (c + 1) * KC;
            int s2 = (c + 1) & 1;
            #pragma unroll
            for (int j = 0; j < 4; j++)
                cpa16(aBase + s2 * aStage + j * 16, aPtr + k1 + j * 4, 16);
            const float* bp = Bm + (size_t)(k1 + bRowT) * Nn;
            #pragma unroll
            for (int j = 0; j < 4; j++) {
                int col = bCol0 + j * 32;
                int sz = (n0 + col < Nn) ? 16 : 0;
                cpa16(bBase + s2 * bStage + j * 32 * 4, bp + n0 + col, sz);
            }
            asm volatile("cp.async.commit_group;");
            asm volatile("cp.async.wait_group 1;");
        } else {
            asm volatile("cp.async.wait_group 0;");
        }
        __syncthreads();

        #pragma unroll
        for (int ks = 0; ks < 4; ks++) {
            uint32_t af[4][4], bf[4][2];
            #pragma unroll
            for (int mt = 0; mt < 4; mt++) {
                int mr = warpM * 64 + mt * 16 + g;
                af[mt][0] = __float_as_uint(AS(st, mr,     ks * 8 + tg));
                af[mt][1] = __float_as_uint(AS(st, mr + 8, ks * 8 + tg));
                af[mt][2] = __float_as_uint(AS(st, mr,     ks * 8 + tg + 4));
                af[mt][3] = __float_as_uint(AS(st, mr + 8, ks * 8 + tg + 4));
            }
            #pragma unroll
            for (int nt = 0; nt < 4; nt++) {
                int nc = warpN * 32 + nt * 8 + g;
                bf[nt][0] = __float_as_uint(BS(st, ks * 8 + tg,     nc));
                bf[nt][1] = __float_as_uint(BS(st, ks * 8 + tg + 4, nc));
            }
            #pragma unroll
            for (int mt = 0; mt < 4; mt++)
                #pragma unroll
                for (int nt = 0; nt < 4; nt++)
                    asm volatile(
                        "mma.sync.aligned.m16n8k8.row.col.f32.tf32.tf32.f32 "
                        "{%0,%1,%2,%3}, {%4,%5,%6,%7}, {%8,%9}, {%0,%1,%2,%3};"
                        : "+f"(acc[mt][nt][0]), "+f"(acc[mt][nt][1]),
                          "+f"(acc[mt][nt][2]), "+f"(acc[mt][nt][3])
                        : "r"(af[mt][0]), "r"(af[mt][1]), "r"(af[mt][2]), "r"(af[mt][3]),
                          "r"(bf[nt][0]), "r"(bf[nt][1]));
        }
        __syncthreads();
    }

    // epilogue (float2 stores; Nn is even, c0 even => pair in-bounds together)
    #pragma unroll
    for (int mt = 0; mt < 4; mt++) {
        int r0 = m0 + warpM * 64 + mt * 16 + g;
        #pragma unroll
        for (int nt = 0; nt < 4; nt++) {
            int c0 = n0 + warpN * 32 + nt * 8 + tg * 2;
            if (c0 < Nn) {
                float b0 = (bias && c0 < nBias) ? bias[c0] : 0.f;
                float b1 = (bias && c0 + 1 < nBias) ? bias[c0 + 1] : 0.f;
                float2 v0 = make_float2(acc[mt][nt][0] + b0, acc[mt][nt][1] + b1);
                float2 v1 = make_float2(acc[mt][nt][2] + b0, acc[mt][nt][3] + b1);
                *reinterpret_cast<float2*>(&Cc[(size_t)r0 * Nn + c0]) = v0;
                *reinterpret_cast<float2*>(&Cc[(size_t)(r0 + 8) * Nn + c0]) = v1;
            }
        }
    }
}

// ---------------- dedicated N=3, K=832 GEMM (offset convs of k=1 layers) ------
__global__ void k_gemm_n3(const float* __restrict__ A, const float* __restrict__ Bm,
                          const float* __restrict__ bias, float* __restrict__ out) {
    __shared__ float Bs[832 * 3];
    int tid = threadIdx.x;
    for (int i = tid; i < 832 * 3; i += 256) Bs[i] = Bm[i];
    __syncthreads();
    int warp = tid >> 5, lane = tid & 31;
    int m = blockIdx.x * 8 + warp;
    const float4* aRow = reinterpret_cast<const float4*>(A + (size_t)m * 832);
    float s0 = 0.f, s1 = 0.f, s2 = 0.f;
    #pragma unroll
    for (int j = 0; j < 7; j++) {
        int q = lane + j * 32;
        if (q < 208) {
            float4 v = aRow[q];
            int k = q * 4;
            s0 = fmaf(v.x, Bs[(k+0)*3+0], s0); s1 = fmaf(v.x, Bs[(k+0)*3+1], s1); s2 = fmaf(v.x, Bs[(k+0)*3+2], s2);
            s0 = fmaf(v.y, Bs[(k+1)*3+0], s0); s1 = fmaf(v.y, Bs[(k+1)*3+1], s1); s2 = fmaf(v.y, Bs[(k+1)*3+2], s2);
            s0 = fmaf(v.z, Bs[(k+2)*3+0], s0); s1 = fmaf(v.z, Bs[(k+2)*3+1], s1); s2 = fmaf(v.z, Bs[(k+2)*3+2], s2);
            s0 = fmaf(v.w, Bs[(k+3)*3+0], s0); s1 = fmaf(v.w, Bs[(k+3)*3+1], s1); s2 = fmaf(v.w, Bs[(k+3)*3+2], s2);
        }
    }
    #pragma unroll
    for (int o = 16; o; o >>= 1) {
        s0 += __shfl_xor_sync(0xffffffffu, s0, o);
        s1 += __shfl_xor_sync(0xffffffffu, s1, o);
        s2 += __shfl_xor_sync(0xffffffffu, s2, o);
    }
    if (lane == 0) {
        out[(size_t)m * 3 + 0] = s0 + bias[0];
        out[(size_t)m * 3 + 1] = s1 + bias[1];
        out[(size_t)m * 3 + 2] = s2 + bias[2];
    }
}

// ---------------- trilinear sampling: samp[m][kk][c] (tf32-rounded output) ----
__global__ void k_sample(const float* __restrict__ src, const float* __restrict__ off,
                         float* __restrict__ samp, int C, int k, int pad, int offStride) {
    int m  = blockIdx.x;
    int kk = blockIdx.y;
    int K  = gridDim.y;
    int b = m / SPA, s = m - b * SPA;
    int t = s / (HH * WW); int rem = s - t * HH * WW;
    int h = rem / WW, w = rem - h * WW;
    int kt = kk / (k * k), kh = (kk / k) % k, kw = kk % k;
    const float* op = off + (size_t)m * offStride + kk * 3;
    float tc = (float)(t - pad + kt) + op[0];
    float hc = (float)(h - pad + kh) + op[1];
    float wc = (float)(w - pad + kw) + op[2];
    float tf = floorf(tc), hf = floorf(hc), wf = floorf(wc);
    float ft = tc - tf, fh = hc - hf, fw = wc - wf;
    int t0 = (int)tf, h0 = (int)hf, w0 = (int)wf;

    float wgt[8]; const float* ptr[8];
    #pragma unroll
    for (int ci = 0; ci < 8; ci++) {
        int dt = ci >> 2, dh = (ci >> 1) & 1, dw = ci & 1;
        int ti = t0 + dt, hi = h0 + dh, wi = w0 + dw;
        bool valid = (ti >= 0) && (ti < TT) && (hi >= 0) && (hi < HH) && (wi >= 0) && (wi < WW);
        float wv = (dt ? ft : 1.f - ft) * (dh ? fh : 1.f - fh) * (dw ? fw : 1.f - fw);
        wgt[ci] = valid ? wv : 0.f;
        int tic = min(max(ti, 0), TT - 1);
        int hic = min(max(hi, 0), HH - 1);
        int wic = min(max(wi, 0), WW - 1);
        ptr[ci] = src + ((size_t)b * SPA + (tic * HH + hic) * WW + wic) * C;
    }
    float* dst = samp + ((size_t)m * K + kk) * C;
    for (int c = threadIdx.x * 4; c < C; c += blockDim.x * 4) {
        float4 acc = make_float4(0.f, 0.f, 0.f, 0.f);
        #pragma unroll
        for (int ci = 0; ci < 8; ci++) {
            float4 v = *reinterpret_cast<const float4*>(ptr[ci] + c);
            acc.x = fmaf(wgt[ci], v.x, acc.x);
            acc.y = fmaf(wgt[ci], v.y, acc.y);
            acc.z = fmaf(wgt[ci], v.z, acc.z);
            acc.w = fmaf(wgt[ci], v.w, acc.w);
        }
        acc.x = f2tff(acc.x); acc.y = f2tff(acc.y);
        acc.z = f2tff(acc.z); acc.w = f2tff(acc.w);
        *reinterpret_cast<float4*>(dst + c) = acc;
    }
}

// ---------------- im2col (k=3, pad=1, integer taps; tf32-rounded output) ------
__global__ void k_im2col(const float* __restrict__ src, float* __restrict__ outm, int C) {
    int m  = blockIdx.x;
    int kk = blockIdx.y;
    int K  = gridDim.y;
    int b = m / SPA, s = m - b * SPA;
    int t = s / (HH * WW); int rem = s - t * HH * WW;
    int h = rem / WW, w = rem - h * WW;
    int kt = kk / 9, kh = (kk / 3) % 3, kw = kk % 3;
    int ti = t + kt - 1, hi = h + kh - 1, wi = w + kw - 1;
    bool valid = (ti >= 0) && (ti < TT) && (hi >= 0) && (hi < HH) && (wi >= 0) && (wi < WW);
    int sidx = valid ? (ti * HH + hi) * WW + wi : 0;
    const float* sp = src + ((size_t)b * SPA + sidx) * C;
    float* dst = outm + ((size_t)m * K + kk) * C;
    for (int c = threadIdx.x * 4; c < C; c += blockDim.x * 4) {
        float4 v = valid ? *reinterpret_cast<const float4*>(sp + c)
                         : make_float4(0.f, 0.f, 0.f, 0.f);
        v.x = f2tff(v.x); v.y = f2tff(v.y);
        v.z = f2tff(v.z); v.w = f2tff(v.w);
        *reinterpret_cast<float4*>(dst + c) = v;
    }
}

// ---------------- per-channel batch stats (mean, biased var) ------------------
__global__ void k_stats(const float* __restrict__ Cm, float* __restrict__ stats, int Nn) {
    int n = blockIdx.x * 32 + threadIdx.x;
    float s = 0.f, s2 = 0.f;
    if (n < Nn) {
        for (int m = threadIdx.y; m < MTOT; m += 8) {
            float v = Cm[(size_t)m * Nn + n];
            s += v; s2 += v * v;
        }
    }
    __shared__ float sh[8][32], sh2[8][32];
    sh[threadIdx.y][threadIdx.x] = s;
    sh2[threadIdx.y][threadIdx.x] = s2;
    __syncthreads();
    if (threadIdx.y == 0 && n < Nn) {
        #pragma unroll
        for (int i = 1; i < 8; i++) { s += sh[i][threadIdx.x]; s2 += sh2[i][threadIdx.x]; }
        float mean = s / (float)MTOT;
        float var  = s2 / (float)MTOT - mean * mean;
        stats[n]       = mean;
        stats[512 + n] = var;
    }
}

// ---------------- BN + ReLU + layout write ------------------------------------
__global__ void k_bnout(const float* __restrict__ Cm, const float* __restrict__ stats,
                        const float* __restrict__ gamma, const float* __restrict__ beta,
                        float* __restrict__ outp, int Nn, int mode, int ch0) {
    size_t idx = (size_t)blockIdx.x * blockDim.x + threadIdx.x;
    size_t tot = (size_t)MTOT * Nn;
    if (idx >= tot) return;
    if (mode == 0) {
        int n = (int)(idx % Nn);
        float sc = gamma[n] * rsqrtf(stats[512 + n] + 1e-5f);
        float v  = fmaf(Cm[idx] - stats[n], sc, beta[n]);
        outp[idx] = fmaxf(v, 0.f);
    } else {
        int s = (int)(idx % SPA); size_t rest = idx / SPA;
        int n = (int)(rest % Nn); int b = (int)(rest / Nn);
        float sc = gamma[n] * rsqrtf(stats[512 + n] + 1e-5f);
        float v  = fmaf(Cm[((size_t)b * SPA + s) * Nn + n] - stats[n], sc, beta[n]);
        outp[((size_t)b * 832 + ch0 + n) * SPA + s] = fmaxf(v, 0.f);
    }
}

// ============================ host orchestration ==============================
static const int GEMM_SMEM = (2 * 128 * 36 + 2 * 32 * 132) * 4;  // 70,656 B

static void run_gemm_pipe(const float* A, const float* Bm, const float* bias, int nBias,
                          float* C, int Nn, int Kn) {
    cudaFuncSetAttribute(k_gemm_pipe, cudaFuncAttributeMaxDynamicSharedMemorySize, GEMM_SMEM);
    dim3 grid((Nn + 127) / 128, MTOT / 128);
    k_gemm_pipe<<<grid, 256, GEMM_SMEM>>>(A, Bm, bias, nBias, C, Nn, Kn);
}

static int sample_block(int C) { return C >= 512 ? 128 : (C >= 128 ? 64 : 32); }

static void run_k1(const float* srcT, int Cin, int Cout,
                   const float* woffT, const float* boffp, const float* wTp,
                   const float* g, const float* bt,
                   float* offb, float* samp, float* conv, float* stats,
                   float* outp, int mode, int ch0) {
    k_gemm_n3<<<MTOT / 8, 256>>>(srcT, woffT, boffp, offb);          // Cin == 832 always here
    k_sample<<<dim3(MTOT, 1), sample_block(Cin)>>>(srcT, offb, samp, Cin, 1, 0, 3);
    run_gemm_pipe(samp, wTp, nullptr, 0, conv, Cout, Cin);
    k_stats<<<(Cout + 31) / 32, dim3(32, 8)>>>(conv, stats, Cout);
    size_t tot = (size_t)MTOT * Cout;
    k_bnout<<<(unsigned)((tot + 255) / 256), 256>>>(conv, stats, g, bt, outp, Cout, mode, ch0);
}

static void run_k3(const float* srcT, int Cin, int Cout,
                   const float* woffT, const float* boffp, const float* wTp,
                   const float* g, const float* bt,
                   float* offb, float* samp, float* conv, float* stats,
                   float* outp, int mode, int ch0) {
    int Kd = 27 * Cin;
    k_im2col<<<dim3(MTOT, 27), sample_block(Cin)>>>(srcT, samp, Cin);
    run_gemm_pipe(samp, woffT, boffp, 81, offb, 96, Kd);   // offsets padded N=96
    k_sample<<<dim3(MTOT, 27), sample_block(Cin)>>>(srcT, offb, samp, Cin, 3, 1, 96);
    run_gemm_pipe(samp, wTp, nullptr, 0, conv, Cout, Kd);
    k_stats<<<(Cout + 31) / 32, dim3(32, 8)>>>(conv, stats, Cout);
    size_t tot = (size_t)MTOT * Cout;
    k_bnout<<<(unsigned)((tot + 255) / 256), 256>>>(conv, stats, g, bt, outp, Cout, mode, ch0);
}

extern "C" void kernel_launch(void* const* d_in, const int* in_sizes, int n_in,
                              void* d_out, int out_size) {
    const float* x = (const float*)d_in[0];
    const float *woff[6], *boff[6], *wcv[6], *gam[6], *bet[6];
    for (int i = 0; i < 6; i++) {
        woff[i] = (const float*)d_in[1 + 5 * i];
        boff[i] = (const float*)d_in[2 + 5 * i];
        wcv[i]  = (const float*)d_in[3 + 5 * i];
        gam[i]  = (const float*)d_in[4 + 5 * i];
        bet[i]  = (const float*)d_in[5 + 5 * i];
    }
    float *xT, *xmT, *x1a, *x2a, *samp, *conv, *offb, *stats, *wT, *woffT;
    cudaGetSymbolAddress((void**)&xT,    g_xT);
    cudaGetSymbolAddress((void**)&xmT,   g_xmT);
    cudaGetSymbolAddress((void**)&x1a,   g_x1a);
    cudaGetSymbolAddress((void**)&x2a,   g_x2a);
    cudaGetSymbolAddress((void**)&samp,  g_samp);
    cudaGetSymbolAddress((void**)&conv,  g_conv);
    cudaGetSymbolAddress((void**)&offb,  g_offb);
    cudaGetSymbolAddress((void**)&stats, g_stats);
    cudaGetSymbolAddress((void**)&wT,    g_wT);
    cudaGetSymbolAddress((void**)&woffT, g_woffT);
    float* out = (float*)d_out;

    // 1) channels-last x
    k_transpose_cl<<<dim3(SPA / 32, 832 / 32, BB), dim3(32, 8)>>>(x, xT);

    // 2) fused weight transposes (main conv + offset conv, all 6 layers)
    const int CIN[6]  = {832, 832, 160, 832, 32, 832};
    const int COUT[6] = {256, 160, 320, 32, 128, 128};
    const int KK[6]   = {1, 1, 27, 1, 27, 1};
    size_t wtoff[6], wooff[6];
    {
        size_t a = 0, bsz = 0;
        for (int i = 0; i < 6; i++) { wtoff[i] = a; a += (size_t)KK[i] * CIN[i] * COUT[i]; }
        for (int i = 0; i < 6; i++) {
            wooff[i] = bsz;
            bsz += (KK[i] == 1) ? (size_t)CIN[i] * 3 : (size_t)KK[i] * CIN[i] * 96;
        }
    }
    {
        WJobs jb;
        int pos = 0;
        for (int i = 0; i < 6; i++) {                 // jobs 0..5: main conv (tf32)
            jb.src[i] = wcv[i]; jb.dst[i] = wT + wtoff[i];
            jb.cout[i] = COUT[i]; jb.coutpad[i] = COUT[i];
            jb.cin[i] = CIN[i]; jb.kk[i] = KK[i]; jb.cvt[i] = 1;
            jb.start[i] = pos; pos += KK[i] * CIN[i] * COUT[i];
        }
        for (int i = 0; i < 6; i++) {                 // jobs 6..11: offset conv
            int j = 6 + i;
            jb.src[j] = woff[i]; jb.dst[j] = woffT + wooff[i];
            if (KK[i] == 1) { jb.cout[j] = 3;  jb.coutpad[j] = 3;  jb.cvt[j] = 0; }
            else            { jb.cout[j] = 81; jb.coutpad[j] = 96; jb.cvt[j] = 1; }
            jb.cin[j] = CIN[i]; jb.kk[j] = KK[i];
            jb.start[j] = pos;
            pos += (KK[i] == 1) ? CIN[i] * 3 : KK[i] * CIN[i] * 96;
        }
        jb.start[12] = pos;
        k_wtrans_all<<<(pos + 255) / 256, 256>>>(jb);
    }

    // 3) branch 0: deform(x, 832->256, k=1) -> out channels [0,256)
    run_k1(xT, 832, 256, woffT + wooff[0], boff[0], wT + wtoff[0], gam[0], bet[0],
           offb, samp, conv, stats, out, 1, 0);

    // 4) branch 1: deform(x, 832->160, k=1) -> x1a ; deform(x1a, 160->320, k=3) -> [256,576)
    run_k1(xT, 832, 160, woffT + wooff[1], boff[1], wT + wtoff[1], gam[1], bet[1],
           offb, samp, conv, stats, x1a, 0, 0);
    run_k3(x1a, 160, 320, woffT + wooff[2], boff[2], wT + wtoff[2], gam[2], bet[2],
           offb, samp, conv, stats, out, 1, 256);

    // 5) branch 2: deform(x, 832->32, k=1) -> x2a ; deform(x2a, 32->128, k=3) -> [576,704)
    run_k1(xT, 832, 32, woffT + wooff[3], boff[3], wT + wtoff[3], gam[3], bet[3],
           offb, samp, conv, stats, x2a, 0, 0);
    run_k3(x2a, 32, 128, woffT + wooff[4], boff[4], wT + wtoff[4], gam[4], bet[4],
           offb, samp, conv, stats, out, 1, 576);

    // 6) branch 3: separable maxpool -> deform(xm, 832->128, k=1) -> [704,832)
    {
        float* tmp1 = samp;
        float* tmp2 = samp + (size_t)MTOT * 832;
        int nthr = (int)(((size_t)MTOT * 208 + 255) / 256);
        k_max3<<<nthr, 256>>>(xT,   tmp1, 1,       WW);
        k_max3<<<nthr, 256>>>(tmp1, tmp2, WW,      HH);
        k_max3<<<nthr, 256>>>(tmp2, xmT,  HH * WW, TT);
    }
    run_k1(xmT, 832, 128, woffT + wooff[5], boff[5], wT + wtoff[5], gam[5], bet[5],
           offb, samp, conv, stats, out, 1, 704);
}

// round 7
// speedup vs baseline: 2.7131x; 1.3744x over previous
#include <cuda_runtime.h>
#include <math.h>
#include <stdint.h>

// Problem constants
#define BB   8
#define TT   8
#define HH   14
#define WW   14
#define SPA  1568          // T*H*W
#define MTOT 12544         // B*SPA
#define KC   32            // GEMM k-chunk

// ---------------- scratch (device globals; no allocation allowed) -------------
__device__ float g_xT [(size_t)MTOT * 832];   // x channels-last
__device__ float g_xmT[(size_t)MTOT * 832];   // maxpool(x) channels-last
__device__ float g_x1a[(size_t)MTOT * 160];   // branch1 intermediate
__device__ float g_x2a[(size_t)MTOT * 32];    // branch2 intermediate
__device__ float g_samp[(size_t)MTOT * 4320]; // im2col / sampled rows (tf32 bits)
__device__ float g_conv[(size_t)MTOT * 320];  // raw conv output (max layer2)
__device__ float g_offb[(size_t)MTOT * 96];   // offset field (stride 96 for k=3)
__device__ float g_stats[1024];               // [0..511]=mean, [512..1023]=var
__device__ float g_wT  [1972224];             // transposed main-conv weights (tf32)
__device__ float g_woffT[520000];             // transposed offset-conv weights

__device__ __forceinline__ uint32_t f2tf(float x) {
    uint32_t u; asm("cvt.rna.tf32.f32 %0, %1;" : "=r"(u) : "f"(x)); return u;
}
__device__ __forceinline__ float f2tff(float x) { return __uint_as_float(f2tf(x)); }

__device__ __forceinline__ void cpa16(uint32_t dst, const void* src, int szBytes) {
    asm volatile("cp.async.cg.shared.global [%0], [%1], 16, %2;"
                 :: "r"(dst), "l"(src), "r"(szBytes));
}

// ---------------- fused prep: transpose x (channels-last) + all weight jobs ---
struct WJobs {
    const float* src[12];
    float*       dst[12];
    int cout[12], coutpad[12], cin[12], kk[12], cvt[12];
    int start[13];
};
#define NT_BLOCKS (49 * 26 * 8)   // transpose tiles: (SPA/32) * (832/32) * B

__global__ void k_prep(WJobs jb, const float* __restrict__ x, float* __restrict__ xT) {
    int bid = blockIdx.x;
    if (bid < NT_BLOCKS) {
        __shared__ float tile[32][33];
        int sx = bid % 49;
        int cy = (bid / 49) % 26;
        int b  = bid / (49 * 26);
        int s0 = sx * 32, c0 = cy * 32;
        int tx = threadIdx.x % 32, ty = threadIdx.x / 32;
        #pragma unroll
        for (int i = ty; i < 32; i += 8)
            tile[i][tx] = x[((size_t)b * 832 + (c0 + i)) * SPA + s0 + tx];
        __syncthreads();
        #pragma unroll
        for (int i = ty; i < 32; i += 8)
            xT[((size_t)b * SPA + (s0 + i)) * 832 + c0 + tx] = tile[tx][i];
    } else {
        int idx = (bid - NT_BLOCKS) * 256 + threadIdx.x;
        if (idx >= jb.start[12]) return;
        int j = 0;
        #pragma unroll
        for (int i = 1; i < 12; i++) if (idx >= jb.start[i]) j = i;
        int local = idx - jb.start[j];
        int cp = jb.coutpad[j], ci = jb.cin[j], K = jb.kk[j];
        int oc = local % cp; int rest = local / cp;
        int c  = rest % ci;  int kk = rest / ci;
        float v = (oc < jb.cout[j]) ? jb.src[j][((size_t)oc * ci + c) * K + kk] : 0.f;
        if (jb.cvt[j]) v = __uint_as_float(f2tf(v));
        jb.dst[j][local] = v;
    }
}

// ---------------- separable 3-max along one dim, channels-last ----------------
__global__ void k_max3(const float* __restrict__ in, float* __restrict__ out,
                       int ddiv, int dmod) {
    size_t idx = (size_t)blockIdx.x * blockDim.x + threadIdx.x;
    if (idx >= (size_t)MTOT * 208) return;
    int c4 = (int)(idx % 208);
    size_t m = idx / 208;
    int s = (int)(m % SPA);
    int coord = (s / ddiv) % dmod;
    const float4* p = reinterpret_cast<const float4*>(in) + m * 208 + c4;
    float4 v = *p;
    if (coord > 0) {
        float4 u = *(p - (size_t)ddiv * 208);
        v.x = fmaxf(v.x, u.x); v.y = fmaxf(v.y, u.y);
        v.z = fmaxf(v.z, u.z); v.w = fmaxf(v.w, u.w);
    }
    if (coord < dmod - 1) {
        float4 u = *(p + (size_t)ddiv * 208);
        v.x = fmaxf(v.x, u.x); v.y = fmaxf(v.y, u.y);
        v.z = fmaxf(v.z, u.z); v.w = fmaxf(v.w, u.w);
    }
    reinterpret_cast<float4*>(out)[m * 208 + c4] = v;
}

// ---------------- pipelined tf32 GEMM: C[M,N] = A[M,K] @ B[K,N] (+bias) -------
#define AS(st, m, k) sm[(size_t)(st) * (128 * 36) + (m) * 36 + (k)]
#define BS(st, k, n) sm[(size_t)(2 * 128 * 36) + (st) * (32 * 132) + (k) * 132 + (n)]

__global__ __launch_bounds__(256) void k_gemm_pipe(
    const float* __restrict__ A, const float* __restrict__ Bm,
    const float* __restrict__ bias, int nBias,
    float* __restrict__ Cc, int Nn, int Kn)
{
    extern __shared__ float sm[];
    int tid = threadIdx.x;
    int lane = tid & 31, warp = tid >> 5;
    int warpM = warp & 1, warpN = warp >> 1;
    int m0 = blockIdx.y * 128, n0 = blockIdx.x * 128;
    int g = lane >> 2, tg = lane & 3;

    float acc[4][4][4];
    #pragma unroll
    for (int i = 0; i < 4; i++)
        #pragma unroll
        for (int j = 0; j < 4; j++)
            #pragma unroll
            for (int q = 0; q < 4; q++) acc[i][j][q] = 0.f;

    const int aRowT = tid >> 1;
    const int aCol0 = (tid & 1) * 16;
    const float* aPtr = A + (size_t)(m0 + aRowT) * Kn + aCol0;
    const int bRowT = tid >> 3;
    const int bCol0 = (tid & 7) * 4;

    uint32_t aBase = (uint32_t)__cvta_generic_to_shared(&AS(0, aRowT, aCol0));
    uint32_t bBase = (uint32_t)__cvta_generic_to_shared(&BS(0, bRowT, bCol0));
    const uint32_t aStage = 128 * 36 * 4;
    const uint32_t bStage = 32 * 132 * 4;

    int nChunks = Kn / KC;

    {
        #pragma unroll
        for (int j = 0; j < 4; j++)
            cpa16(aBase + j * 16, aPtr + j * 4, 16);
        const float* bp = Bm + (size_t)bRowT * Nn;
        #pragma unroll
        for (int j = 0; j < 4; j++) {
            int col = bCol0 + j * 32;
            int sz = (n0 + col < Nn) ? 16 : 0;
            cpa16(bBase + j * 32 * 4, bp + n0 + col, sz);
        }
        asm volatile("cp.async.commit_group;");
    }

    for (int c = 0; c < nChunks; c++) {
        int st = c & 1;
        if (c + 1 < nChunks) {
            int k1 = (c + 1) * KC;
            int s2 = (c + 1) & 1;
            #pragma unroll
            for (int j = 0; j < 4; j++)
                cpa16(aBase + s2 * aStage + j * 16, aPtr + k1 + j * 4, 16);
            const float* bp = Bm + (size_t)(k1 + bRowT) * Nn;
            #pragma unroll
            for (int j = 0; j < 4; j++) {
                int col = bCol0 + j * 32;
                int sz = (n0 + col < Nn) ? 16 : 0;
                cpa16(bBase + s2 * bStage + j * 32 * 4, bp + n0 + col, sz);
            }
            asm volatile("cp.async.commit_group;");
            asm volatile("cp.async.wait_group 1;");
        } else {
            asm volatile("cp.async.wait_group 0;");
        }
        __syncthreads();

        #pragma unroll
        for (int ks = 0; ks < 4; ks++) {
            uint32_t af[4][4], bf[4][2];
            #pragma unroll
            for (int mt = 0; mt < 4; mt++) {
                int mr = warpM * 64 + mt * 16 + g;
                af[mt][0] = __float_as_uint(AS(st, mr,     ks * 8 + tg));
                af[mt][1] = __float_as_uint(AS(st, mr + 8, ks * 8 + tg));
                af[mt][2] = __float_as_uint(AS(st, mr,     ks * 8 + tg + 4));
                af[mt][3] = __float_as_uint(AS(st, mr + 8, ks * 8 + tg + 4));
            }
            #pragma unroll
            for (int nt = 0; nt < 4; nt++) {
                int nc = warpN * 32 + nt * 8 + g;
                bf[nt][0] = __float_as_uint(BS(st, ks * 8 + tg,     nc));
                bf[nt][1] = __float_as_uint(BS(st, ks * 8 + tg + 4, nc));
            }
            #pragma unroll
            for (int mt = 0; mt < 4; mt++)
                #pragma unroll
                for (int nt = 0; nt < 4; nt++)
                    asm volatile(
                        "mma.sync.aligned.m16n8k8.row.col.f32.tf32.tf32.f32 "
                        "{%0,%1,%2,%3}, {%4,%5,%6,%7}, {%8,%9}, {%0,%1,%2,%3};"
                        : "+f"(acc[mt][nt][0]), "+f"(acc[mt][nt][1]),
                          "+f"(acc[mt][nt][2]), "+f"(acc[mt][nt][3])
                        : "r"(af[mt][0]), "r"(af[mt][1]), "r"(af[mt][2]), "r"(af[mt][3]),
                          "r"(bf[nt][0]), "r"(bf[nt][1]));
        }
        __syncthreads();
    }

    #pragma unroll
    for (int mt = 0; mt < 4; mt++) {
        int r0 = m0 + warpM * 64 + mt * 16 + g;
        #pragma unroll
        for (int nt = 0; nt < 4; nt++) {
            int c0 = n0 + warpN * 32 + nt * 8 + tg * 2;
            if (c0 < Nn) {
                float b0 = (bias && c0 < nBias) ? bias[c0] : 0.f;
                float b1 = (bias && c0 + 1 < nBias) ? bias[c0 + 1] : 0.f;
                float2 v0 = make_float2(acc[mt][nt][0] + b0, acc[mt][nt][1] + b1);
                float2 v1 = make_float2(acc[mt][nt][2] + b0, acc[mt][nt][3] + b1);
                *reinterpret_cast<float2*>(&Cc[(size_t)r0 * Nn + c0]) = v0;
                *reinterpret_cast<float2*>(&Cc[(size_t)(r0 + 8) * Nn + c0]) = v1;
            }
        }
    }
}

// ---------------- dedicated N=3, K=832 GEMM (offset convs of k=1 layers) ------
__global__ void k_gemm_n3(const float* __restrict__ A, const float* __restrict__ Bm,
                          const float* __restrict__ bias, float* __restrict__ out) {
    __shared__ float Bs[832 * 3];
    int tid = threadIdx.x;
    for (int i = tid; i < 832 * 3; i += 256) Bs[i] = Bm[i];
    __syncthreads();
    int warp = tid >> 5, lane = tid & 31;
    int m = blockIdx.x * 8 + warp;
    const float4* aRow = reinterpret_cast<const float4*>(A + (size_t)m * 832);
    float s0 = 0.f, s1 = 0.f, s2 = 0.f;
    #pragma unroll
    for (int j = 0; j < 7; j++) {
        int q = lane + j * 32;
        if (q < 208) {
            float4 v = aRow[q];
            int k = q * 4;
            s0 = fmaf(v.x, Bs[(k+0)*3+0], s0); s1 = fmaf(v.x, Bs[(k+0)*3+1], s1); s2 = fmaf(v.x, Bs[(k+0)*3+2], s2);
            s0 = fmaf(v.y, Bs[(k+1)*3+0], s0); s1 = fmaf(v.y, Bs[(k+1)*3+1], s1); s2 = fmaf(v.y, Bs[(k+1)*3+2], s2);
            s0 = fmaf(v.z, Bs[(k+2)*3+0], s0); s1 = fmaf(v.z, Bs[(k+2)*3+1], s1); s2 = fmaf(v.z, Bs[(k+2)*3+2], s2);
            s0 = fmaf(v.w, Bs[(k+3)*3+0], s0); s1 = fmaf(v.w, Bs[(k+3)*3+1], s1); s2 = fmaf(v.w, Bs[(k+3)*3+2], s2);
        }
    }
    #pragma unroll
    for (int o = 16; o; o >>= 1) {
        s0 += __shfl_xor_sync(0xffffffffu, s0, o);
        s1 += __shfl_xor_sync(0xffffffffu, s1, o);
        s2 += __shfl_xor_sync(0xffffffffu, s2, o);
    }
    if (lane == 0) {
        out[(size_t)m * 3 + 0] = s0 + bias[0];
        out[(size_t)m * 3 + 1] = s1 + bias[1];
        out[(size_t)m * 3 + 2] = s2 + bias[2];
    }
}

// ---------------- k=1 trilinear sampling (one tap) ----------------------------
__global__ void k_sample(const float* __restrict__ src, const float* __restrict__ off,
                         float* __restrict__ samp, int C) {
    int m  = blockIdx.x;
    int b = m / SPA, s = m - b * SPA;
    int t = s / (HH * WW); int rem = s - t * HH * WW;
    int h = rem / WW, w = rem - h * WW;
    const float* op = off + (size_t)m * 3;
    float tc = (float)t + op[0];
    float hc = (float)h + op[1];
    float wc = (float)w + op[2];
    float tf = floorf(tc), hf = floorf(hc), wf = floorf(wc);
    float ft = tc - tf, fh = hc - hf, fw = wc - wf;
    int t0 = (int)tf, h0 = (int)hf, w0 = (int)wf;

    float wgt[8]; const float* ptr[8];
    #pragma unroll
    for (int ci = 0; ci < 8; ci++) {
        int dt = ci >> 2, dh = (ci >> 1) & 1, dw = ci & 1;
        int ti = t0 + dt, hi = h0 + dh, wi = w0 + dw;
        bool valid = (ti >= 0) && (ti < TT) && (hi >= 0) && (hi < HH) && (wi >= 0) && (wi < WW);
        float wv = (dt ? ft : 1.f - ft) * (dh ? fh : 1.f - fh) * (dw ? fw : 1.f - fw);
        wgt[ci] = valid ? wv : 0.f;
        int tic = min(max(ti, 0), TT - 1);
        int hic = min(max(hi, 0), HH - 1);
        int wic = min(max(wi, 0), WW - 1);
        ptr[ci] = src + ((size_t)b * SPA + (tic * HH + hic) * WW + wic) * C;
    }
    float* dst = samp + (size_t)m * C;
    for (int c = threadIdx.x * 4; c < C; c += blockDim.x * 4) {
        float4 acc = make_float4(0.f, 0.f, 0.f, 0.f);
        #pragma unroll
        for (int ci = 0; ci < 8; ci++) {
            float4 v = *reinterpret_cast<const float4*>(ptr[ci] + c);
            acc.x = fmaf(wgt[ci], v.x, acc.x);
            acc.y = fmaf(wgt[ci], v.y, acc.y);
            acc.z = fmaf(wgt[ci], v.z, acc.z);
            acc.w = fmaf(wgt[ci], v.w, acc.w);
        }
        acc.x = f2tff(acc.x); acc.y = f2tff(acc.y);
        acc.z = f2tff(acc.z); acc.w = f2tff(acc.w);
        *reinterpret_cast<float4*>(dst + c) = acc;
    }
}

// ---------------- k=3 trilinear sampling: one CTA per position, 27 taps -------
__global__ void k_sample3(const float* __restrict__ src, const float* __restrict__ off,
                          float* __restrict__ samp, int C) {
    __shared__ float sw[27][8];
    __shared__ int   sb[27][8];
    int m = blockIdx.x;
    int b = m / SPA, s = m - b * SPA;
    int t = s / (HH * WW); int rem = s - t * HH * WW;
    int h = rem / WW, w = rem - h * WW;
    int tid = threadIdx.x;
    if (tid < 27) {
        int kt = tid / 9, kh = (tid / 3) % 3, kw = tid % 3;
        const float* op = off + (size_t)m * 96 + tid * 3;
        float tc = (float)(t - 1 + kt) + op[0];
        float hc = (float)(h - 1 + kh) + op[1];
        float wc = (float)(w - 1 + kw) + op[2];
        float tf = floorf(tc), hf = floorf(hc), wf = floorf(wc);
        float ft = tc - tf, fh = hc - hf, fw = wc - wf;
        int t0 = (int)tf, h0 = (int)hf, w0 = (int)wf;
        #pragma unroll
        for (int ci = 0; ci < 8; ci++) {
            int dt = ci >> 2, dh = (ci >> 1) & 1, dw = ci & 1;
            int ti = t0 + dt, hi = h0 + dh, wi = w0 + dw;
            bool valid = (ti >= 0) && (ti < TT) && (hi >= 0) && (hi < HH) && (wi >= 0) && (wi < WW);
            float wv = (dt ? ft : 1.f - ft) * (dh ? fh : 1.f - fh) * (dw ? fw : 1.f - fw);
            sw[tid][ci] = valid ? wv : 0.f;
            int tic = min(max(ti, 0), TT - 1);
            int hic = min(max(hi, 0), HH - 1);
            int wic = min(max(wi, 0), WW - 1);
            sb[tid][ci] = b * SPA + (tic * HH + hic) * WW + wic;
        }
    }
    __syncthreads();
    int nC4 = C >> 2;
    int items = 27 * nC4;
    float* dst = samp + (size_t)m * 27 * C;
    for (int it = tid; it < items; it += blockDim.x) {
        int kk = it / nC4, c4 = it - kk * nC4;
        float4 acc = make_float4(0.f, 0.f, 0.f, 0.f);
        #pragma unroll
        for (int ci = 0; ci < 8; ci++) {
            float wv = sw[kk][ci];
            const float4* p = reinterpret_cast<const float4*>(src + (size_t)sb[kk][ci] * C) + c4;
            float4 v = *p;
            acc.x = fmaf(wv, v.x, acc.x);
            acc.y = fmaf(wv, v.y, acc.y);
            acc.z = fmaf(wv, v.z, acc.z);
            acc.w = fmaf(wv, v.w, acc.w);
        }
        acc.x = f2tff(acc.x); acc.y = f2tff(acc.y);
        acc.z = f2tff(acc.z); acc.w = f2tff(acc.w);
        reinterpret_cast<float4*>(dst)[(size_t)kk * nC4 + c4] = acc;
    }
}

// ---------------- k=3 im2col: one CTA per position, 27 taps -------------------
__global__ void k_im2col3(const float* __restrict__ src, float* __restrict__ outm, int C) {
    __shared__ int sidx[27];
    __shared__ int svalid[27];
    int m = blockIdx.x;
    int b = m / SPA, s = m - b * SPA;
    int t = s / (HH * WW); int rem = s - t * HH * WW;
    int h = rem / WW, w = rem - h * WW;
    int tid = threadIdx.x;
    if (tid < 27) {
        int kt = tid / 9, kh = (tid / 3) % 3, kw = tid % 3;
        int ti = t + kt - 1, hi = h + kh - 1, wi = w + kw - 1;
        bool valid = (ti >= 0) && (ti < TT) && (hi >= 0) && (hi < HH) && (wi >= 0) && (wi < WW);
        svalid[tid] = valid;
        sidx[tid] = b * SPA + (valid ? (ti * HH + hi) * WW + wi : 0);
    }
    __syncthreads();
    int nC4 = C >> 2;
    int items = 27 * nC4;
    float* dst = outm + (size_t)m * 27 * C;
    for (int it = tid; it < items; it += blockDim.x) {
        int kk = it / nC4, c4 = it - kk * nC4;
        float4 v = make_float4(0.f, 0.f, 0.f, 0.f);
        if (svalid[kk])
            v = reinterpret_cast<const float4*>(src + (size_t)sidx[kk] * C)[c4];
        v.x = f2tff(v.x); v.y = f2tff(v.y);
        v.z = f2tff(v.z); v.w = f2tff(v.w);
        reinterpret_cast<float4*>(dst)[(size_t)kk * nC4 + c4] = v;
    }
}

// ---------------- per-channel batch stats (mean, biased var) ------------------
__global__ void k_stats(const float* __restrict__ Cm, float* __restrict__ stats, int Nn) {
    int n = blockIdx.x * 32 + threadIdx.x;
    float s = 0.f, s2 = 0.f;
    if (n < Nn) {
        for (int m = threadIdx.y; m < MTOT; m += 8) {
            float v = Cm[(size_t)m * Nn + n];
            s += v; s2 += v * v;
        }
    }
    __shared__ float sh[8][32], sh2[8][32];
    sh[threadIdx.y][threadIdx.x] = s;
    sh2[threadIdx.y][threadIdx.x] = s2;
    __syncthreads();
    if (threadIdx.y == 0 && n < Nn) {
        #pragma unroll
        for (int i = 1; i < 8; i++) { s += sh[i][threadIdx.x]; s2 += sh2[i][threadIdx.x]; }
        float mean = s / (float)MTOT;
        float var  = s2 / (float)MTOT - mean * mean;
        stats[n]       = mean;
        stats[512 + n] = var;
    }
}

// ---------------- BN + ReLU, channels-last output (intermediates) -------------
__global__ void k_bnout_cl(const float* __restrict__ Cm, const float* __restrict__ stats,
                           const float* __restrict__ gamma, const float* __restrict__ beta,
                           float* __restrict__ outp, int Nn) {
    size_t idx = (size_t)blockIdx.x * blockDim.x + threadIdx.x;
    size_t tot = (size_t)MTOT * Nn;
    if (idx >= tot) return;
    int n = (int)(idx % Nn);
    float sc = gamma[n] * rsqrtf(stats[512 + n] + 1e-5f);
    float v  = fmaf(Cm[idx] - stats[n], sc, beta[n]);
    outp[idx] = fmaxf(v, 0.f);
}

// ---------------- BN + ReLU + tiled transpose into NCDHW concat output --------
// grid (SPA/32, Nn/32, B); block (32, 8)
__global__ void k_bnout_t(const float* __restrict__ Cm, const float* __restrict__ stats,
                          const float* __restrict__ gamma, const float* __restrict__ beta,
                          float* __restrict__ outp, int Nn, int ch0) {
    __shared__ float tile[32][33];
    int b = blockIdx.z, s0 = blockIdx.x * 32, n0 = blockIdx.y * 32;
    int tx = threadIdx.x, ty = threadIdx.y;
    int n = n0 + tx;
    float mean = stats[n];
    float sc = gamma[n] * rsqrtf(stats[512 + n] + 1e-5f);
    float bt = beta[n];
    #pragma unroll
    for (int i = ty; i < 32; i += 8) {
        float v = fmaf(Cm[((size_t)b * SPA + s0 + i) * Nn + n] - mean, sc, bt);
        tile[i][tx] = fmaxf(v, 0.f);
    }
    __syncthreads();
    #pragma unroll
    for (int i = ty; i < 32; i += 8)
        outp[((size_t)b * 832 + ch0 + n0 + i) * SPA + s0 + tx] = tile[tx][i];
}

// ============================ host orchestration ==============================
static const int GEMM_SMEM = (2 * 128 * 36 + 2 * 32 * 132) * 4;  // 70,656 B

static void run_gemm_pipe(const float* A, const float* Bm, const float* bias, int nBias,
                          float* C, int Nn, int Kn) {
    cudaFuncSetAttribute(k_gemm_pipe, cudaFuncAttributeMaxDynamicSharedMemorySize, GEMM_SMEM);
    dim3 grid((Nn + 127) / 128, MTOT / 128);
    k_gemm_pipe<<<grid, 256, GEMM_SMEM>>>(A, Bm, bias, nBias, C, Nn, Kn);
}

static void run_bn(const float* conv, float* stats, const float* g, const float* bt,
                   float* outp, int Cout, int mode, int ch0) {
    k_stats<<<(Cout + 31) / 32, dim3(32, 8)>>>(conv, stats, Cout);
    if (mode == 0) {
        size_t tot = (size_t)MTOT * Cout;
        k_bnout_cl<<<(unsigned)((tot + 255) / 256), 256>>>(conv, stats, g, bt, outp, Cout);
    } else {
        dim3 grid(SPA / 32, Cout / 32, BB);
        k_bnout_t<<<grid, dim3(32, 8)>>>(conv, stats, g, bt, outp, Cout, ch0);
    }
}

static void run_k1(const float* srcT, int Cin, int Cout,
                   const float* woffT, const float* boffp, const float* wTp,
                   const float* g, const float* bt,
                   float* offb, float* samp, float* conv, float* stats,
                   float* outp, int mode, int ch0) {
    k_gemm_n3<<<MTOT / 8, 256>>>(srcT, woffT, boffp, offb);          // Cin == 832 always
    k_sample<<<MTOT, 128>>>(srcT, offb, samp, Cin);
    run_gemm_pipe(samp, wTp, nullptr, 0, conv, Cout, Cin);
    run_bn(conv, stats, g, bt, outp, Cout, mode, ch0);
}

static void run_k3(const float* srcT, int Cin, int Cout,
                   const float* woffT, const float* boffp, const float* wTp,
                   const float* g, const float* bt,
                   float* offb, float* samp, float* conv, float* stats,
                   float* outp, int mode, int ch0) {
    int Kd = 27 * Cin;
    int blk = (Cin >= 128) ? 256 : 128;
    k_im2col3<<<MTOT, blk>>>(srcT, samp, Cin);
    run_gemm_pipe(samp, woffT, boffp, 81, offb, 96, Kd);   // offsets padded N=96
    k_sample3<<<MTOT, blk>>>(srcT, offb, samp, Cin);
    run_gemm_pipe(samp, wTp, nullptr, 0, conv, Cout, Kd);
    run_bn(conv, stats, g, bt, outp, Cout, mode, ch0);
}

extern "C" void kernel_launch(void* const* d_in, const int* in_sizes, int n_in,
                              void* d_out, int out_size) {
    const float* x = (const float*)d_in[0];
    const float *woff[6], *boff[6], *wcv[6], *gam[6], *bet[6];
    for (int i = 0; i < 6; i++) {
        woff[i] = (const float*)d_in[1 + 5 * i];
        boff[i] = (const float*)d_in[2 + 5 * i];
        wcv[i]  = (const float*)d_in[3 + 5 * i];
        gam[i]  = (const float*)d_in[4 + 5 * i];
        bet[i]  = (const float*)d_in[5 + 5 * i];
    }
    float *xT, *xmT, *x1a, *x2a, *samp, *conv, *offb, *stats, *wT, *woffT;
    cudaGetSymbolAddress((void**)&xT,    g_xT);
    cudaGetSymbolAddress((void**)&xmT,   g_xmT);
    cudaGetSymbolAddress((void**)&x1a,   g_x1a);
    cudaGetSymbolAddress((void**)&x2a,   g_x2a);
    cudaGetSymbolAddress((void**)&samp,  g_samp);
    cudaGetSymbolAddress((void**)&conv,  g_conv);
    cudaGetSymbolAddress((void**)&offb,  g_offb);
    cudaGetSymbolAddress((void**)&stats, g_stats);
    cudaGetSymbolAddress((void**)&wT,    g_wT);
    cudaGetSymbolAddress((void**)&woffT, g_woffT);
    float* out = (float*)d_out;

    const int CIN[6]  = {832, 832, 160, 832, 32, 832};
    const int COUT[6] = {256, 160, 320, 32, 128, 128};
    const int KK[6]   = {1, 1, 27, 1, 27, 1};
    size_t wtoff[6], wooff[6];
    {
        size_t a = 0, bsz = 0;
        for (int i = 0; i < 6; i++) { wtoff[i] = a; a += (size_t)KK[i] * CIN[i] * COUT[i]; }
        for (int i = 0; i < 6; i++) {
            wooff[i] = bsz;
            bsz += (KK[i] == 1) ? (size_t)CIN[i] * 3 : (size_t)KK[i] * CIN[i] * 96;
        }
    }

    // launch #1: fused prep (transpose + all 12 weight transposes)
    {
        WJobs jb;
        int pos = 0;
        for (int i = 0; i < 6; i++) {
            jb.src[i] = wcv[i]; jb.dst[i] = wT + wtoff[i];
            jb.cout[i] = COUT[i]; jb.coutpad[i] = COUT[i];
            jb.cin[i] = CIN[i]; jb.kk[i] = KK[i]; jb.cvt[i] = 1;
            jb.start[i] = pos; pos += KK[i] * CIN[i] * COUT[i];
        }
        for (int i = 0; i < 6; i++) {
            int j = 6 + i;
            jb.src[j] = woff[i]; jb.dst[j] = woffT + wooff[i];
            if (KK[i] == 1) { jb.cout[j] = 3;  jb.coutpad[j] = 3;  jb.cvt[j] = 0; }
            else            { jb.cout[j] = 81; jb.coutpad[j] = 96; jb.cvt[j] = 1; }
            jb.cin[j] = CIN[i]; jb.kk[j] = KK[i];
            jb.start[j] = pos;
            pos += (KK[i] == 1) ? CIN[i] * 3 : KK[i] * CIN[i] * 96;
        }
        jb.start[12] = pos;
        int wBlocks = (pos + 255) / 256;
        k_prep<<<NT_BLOCKS + wBlocks, 256>>>(jb, x, xT);
    }

    // branch 0 (launches #2 n3, #3 sample, #4 gemm_pipe -> profiled)
    run_k1(xT, 832, 256, woffT + wooff[0], boff[0], wT + wtoff[0], gam[0], bet[0],
           offb, samp, conv, stats, out, 1, 0);

    // branch 1
    run_k1(xT, 832, 160, woffT + wooff[1], boff[1], wT + wtoff[1], gam[1], bet[1],
           offb, samp, conv, stats, x1a, 0, 0);
    run_k3(x1a, 160, 320, woffT + wooff[2], boff[2], wT + wtoff[2], gam[2], bet[2],
           offb, samp, conv, stats, out, 1, 256);

    // branch 2
    run_k1(xT, 832, 32, woffT + wooff[3], boff[3], wT + wtoff[3], gam[3], bet[3],
           offb, samp, conv, stats, x2a, 0, 0);
    run_k3(x2a, 32, 128, woffT + wooff[4], boff[4], wT + wtoff[4], gam[4], bet[4],
           offb, samp, conv, stats, out, 1, 576);

    // branch 3: separable maxpool -> deform k=1
    {
        float* tmp1 = samp;
        float* tmp2 = samp + (size_t)MTOT * 832;
        int nthr = (int)(((size_t)MTOT * 208 + 255) / 256);
        k_max3<<<nthr, 256>>>(xT,   tmp1, 1,       WW);
        k_max3<<<nthr, 256>>>(tmp1, tmp2, WW,      HH);
        k_max3<<<nthr, 256>>>(tmp2, xmT,  HH * WW, TT);
    }
    run_k1(xmT, 832, 128, woffT + wooff[5], boff[5], wT + wtoff[5], gam[5], bet[5],
           offb, samp, conv, stats, out, 1, 704);
}

// round 9
// speedup vs baseline: 2.8068x; 1.0345x over previous
#include <cuda_runtime.h>
#include <math.h>
#include <stdint.h>

// Problem constants
#define BB   8
#define TT   8
#define HH   14
#define WW   14
#define SPA  1568          // T*H*W
#define MTOT 12544         // B*SPA
#define KC   32            // GEMM k-chunk

// ---------------- scratch (device globals; no allocation allowed) -------------
__device__ float g_xT [(size_t)MTOT * 832];   // x channels-last
__device__ float g_xmT[(size_t)MTOT * 832];   // maxpool(x) channels-last
__device__ float g_x1a[(size_t)MTOT * 160];   // branch1 intermediate
__device__ float g_x2a[(size_t)MTOT * 32];    // branch2 intermediate
__device__ float g_samp[(size_t)MTOT * 4320]; // im2col / sampled rows (tf32 bits)
__device__ float g_conv[(size_t)MTOT * 320];  // raw conv output (max layer2)
__device__ float g_offb[(size_t)MTOT * 96];   // offset field (stride 96 for k=3)
__device__ float g_stats[1024];               // [0..511]=mean, [512..1023]=var
__device__ float g_wT  [1972224];             // transposed main-conv weights (tf32)
__device__ float g_woffT[520000];             // transposed offset-conv weights

__device__ __forceinline__ uint32_t f2tf(float x) {
    uint32_t u; asm("cvt.rna.tf32.f32 %0, %1;" : "=r"(u) : "f"(x)); return u;
}
__device__ __forceinline__ float f2tff(float x) { return __uint_as_float(f2tf(x)); }

__device__ __forceinline__ void cpa16(uint32_t dst, const void* src, int szBytes) {
    asm volatile("cp.async.cg.shared.global [%0], [%1], 16, %2;"
                 :: "r"(dst), "l"(src), "r"(szBytes));
}

// ---------------- fused prep: transpose x (channels-last) + all weight jobs ---
struct WJobs {
    const float* src[12];
    float*       dst[12];
    int cout[12], coutpad[12], cin[12], kk[12], cvt[12];
    int start[13];
};
#define NT_BLOCKS (49 * 26 * 8)   // transpose tiles: (SPA/32) * (832/32) * B

__global__ void k_prep(WJobs jb, const float* __restrict__ x, float* __restrict__ xT) {
    int bid = blockIdx.x;
    if (bid < NT_BLOCKS) {
        __shared__ float tile[32][33];
        int sx = bid % 49;
        int cy = (bid / 49) % 26;
        int b  = bid / (49 * 26);
        int s0 = sx * 32, c0 = cy * 32;
        int tx = threadIdx.x % 32, ty = threadIdx.x / 32;
        #pragma unroll
        for (int i = ty; i < 32; i += 8)
            tile[i][tx] = x[((size_t)b * 832 + (c0 + i)) * SPA + s0 + tx];
        __syncthreads();
        #pragma unroll
        for (int i = ty; i < 32; i += 8)
            xT[((size_t)b * SPA + (s0 + i)) * 832 + c0 + tx] = tile[tx][i];
    } else {
        int idx = (bid - NT_BLOCKS) * 256 + threadIdx.x;
        if (idx >= jb.start[12]) return;
        int j = 0;
        #pragma unroll
        for (int i = 1; i < 12; i++) if (idx >= jb.start[i]) j = i;
        int local = idx - jb.start[j];
        int cp = jb.coutpad[j], ci = jb.cin[j], K = jb.kk[j];
        int oc = local % cp; int rest = local / cp;
        int c  = rest % ci;  int kk = rest / ci;
        float v = (oc < jb.cout[j]) ? jb.src[j][((size_t)oc * ci + c) * K + kk] : 0.f;
        if (jb.cvt[j]) v = __uint_as_float(f2tf(v));
        jb.dst[j][local] = v;
    }
}

// ---------------- separable 3-max along one dim, channels-last ----------------
__global__ void k_max3(const float* __restrict__ in, float* __restrict__ out,
                       int ddiv, int dmod) {
    size_t idx = (size_t)blockIdx.x * blockDim.x + threadIdx.x;
    if (idx >= (size_t)MTOT * 208) return;
    int c4 = (int)(idx % 208);
    size_t m = idx / 208;
    int s = (int)(m % SPA);
    int coord = (s / ddiv) % dmod;
    const float4* p = reinterpret_cast<const float4*>(in) + m * 208 + c4;
    float4 v = *p;
    if (coord > 0) {
        float4 u = *(p - (size_t)ddiv * 208);
        v.x = fmaxf(v.x, u.x); v.y = fmaxf(v.y, u.y);
        v.z = fmaxf(v.z, u.z); v.w = fmaxf(v.w, u.w);
    }
    if (coord < dmod - 1) {
        float4 u = *(p + (size_t)ddiv * 208);
        v.x = fmaxf(v.x, u.x); v.y = fmaxf(v.y, u.y);
        v.z = fmaxf(v.z, u.z); v.w = fmaxf(v.w, u.w);
    }
    reinterpret_cast<float4*>(out)[m * 208 + c4] = v;
}

// ---------------- pipelined tf32 GEMM: C[M,N] = A[M,K] @ B[K,N] (+bias) -------
// __launch_bounds__(256, 2): cap regs at 128 so 2 CTAs co-reside per SM
// (R7 profile: 138 regs -> 1 CTA/SM -> occ 12.5%, tensor 23.6%).
#define AS(st, m, k) sm[(size_t)(st) * (128 * 36) + (m) * 36 + (k)]
#define BS(st, k, n) sm[(size_t)(2 * 128 * 36) + (st) * (32 * 132) + (k) * 132 + (n)]

__global__ __launch_bounds__(256, 2) void k_gemm_pipe(
    const float* __restrict__ A, const float* __restrict__ Bm,
    const float* __restrict__ bias, int nBias,
    float* __restrict__ Cc, int Nn, int Kn)
{
    extern __shared__ float sm[];
    int tid = threadIdx.x;
    int lane = tid & 31, warp = tid >> 5;
    int warpM = warp & 1, warpN = warp >> 1;
    int m0 = blockIdx.y * 128, n0 = blockIdx.x * 128;
    int g = lane >> 2, tg = lane & 3;

    float acc[4][4][4];
    #pragma unroll
    for (int i = 0; i < 4; i++)
        #pragma unroll
        for (int j = 0; j < 4; j++)
            #pragma unroll
            for (int q = 0; q < 4; q++) acc[i][j][q] = 0.f;

    const int aRowT = tid >> 1;
    const int aCol0 = (tid & 1) * 16;
    const float* aPtr = A + (size_t)(m0 + aRowT) * Kn + aCol0;
    const int bRowT = tid >> 3;
    const int bCol0 = (tid & 7) * 4;

    uint32_t aBase = (uint32_t)__cvta_generic_to_shared(&AS(0, aRowT, aCol0));
    uint32_t bBase = (uint32_t)__cvta_generic_to_shared(&BS(0, bRowT, bCol0));
    const uint32_t aStage = 128 * 36 * 4;
    const uint32_t bStage = 32 * 132 * 4;

    int nChunks = Kn / KC;

    {
        #pragma unroll
        for (int j = 0; j < 4; j++)
            cpa16(aBase + j * 16, aPtr + j * 4, 16);
        const float* bp = Bm + (size_t)bRowT * Nn;
        #pragma unroll
        for (int j = 0; j < 4; j++) {
            int col = bCol0 + j * 32;
            int sz = (n0 + col < Nn) ? 16 : 0;
            cpa16(bBase + j * 32 * 4, bp + n0 + col, sz);
        }
        asm volatile("cp.async.commit_group;");
    }

    for (int c = 0; c < nChunks; c++) {
        int st = c & 1;
        if (c + 1 < nChunks) {
            int k1 = (c + 1) * KC;
            int s2 = (c + 1) & 1;
            #pragma unroll
            for (int j = 0; j < 4; j++)
                cpa16(aBase + s2 * aStage + j * 16, aPtr + k1 + j * 4, 16);
            const float* bp = Bm + (size_t)(k1 + bRowT) * Nn;
            #pragma unroll
            for (int j = 0; j < 4; j++) {
                int col = bCol0 + j * 32;
                int sz = (n0 + col < Nn) ? 16 : 0;
                cpa16(bBase + s2 * bStage + j * 32 * 4, bp + n0 + col, sz);
            }
            asm volatile("cp.async.commit_group;");
            asm volatile("cp.async.wait_group 1;");
        } else {
            asm volatile("cp.async.wait_group 0;");
        }
        __syncthreads();

        #pragma unroll
        for (int ks = 0; ks < 4; ks++) {
            uint32_t af[4][4], bf[4][2];
            #pragma unroll
            for (int mt = 0; mt < 4; mt++) {
                int mr = warpM * 64 + mt * 16 + g;
                af[mt][0] = __float_as_uint(AS(st, mr,     ks * 8 + tg));
                af[mt][1] = __float_as_uint(AS(st, mr + 8, ks * 8 + tg));
                af[mt][2] = __float_as_uint(AS(st, mr,     ks * 8 + tg + 4));
                af[mt][3] = __float_as_uint(AS(st, mr + 8, ks * 8 + tg + 4));
            }
            #pragma unroll
            for (int nt = 0; nt < 4; nt++) {
                int nc = warpN * 32 + nt * 8 + g;
                bf[nt][0] = __float_as_uint(BS(st, ks * 8 + tg,     nc));
                bf[nt][1] = __float_as_uint(BS(st, ks * 8 + tg + 4, nc));
            }
            #pragma unroll
            for (int mt = 0; mt < 4; mt++)
                #pragma unroll
                for (int nt = 0; nt < 4; nt++)
                    asm volatile(
                        "mma.sync.aligned.m16n8k8.row.col.f32.tf32.tf32.f32 "
                        "{%0,%1,%2,%3}, {%4,%5,%6,%7}, {%8,%9}, {%0,%1,%2,%3};"
                        : "+f"(acc[mt][nt][0]), "+f"(acc[mt][nt][1]),
                          "+f"(acc[mt][nt][2]), "+f"(acc[mt][nt][3])
                        : "r"(af[mt][0]), "r"(af[mt][1]), "r"(af[mt][2]), "r"(af[mt][3]),
                          "r"(bf[nt][0]), "r"(bf[nt][1]));
        }
        __syncthreads();
    }

    #pragma unroll
    for (int mt = 0; mt < 4; mt++) {
        int r0 = m0 + warpM * 64 + mt * 16 + g;
        #pragma unroll
        for (int nt = 0; nt < 4; nt++) {
            int c0 = n0 + warpN * 32 + nt * 8 + tg * 2;
            if (c0 < Nn) {
                float b0 = (bias && c0 < nBias) ? bias[c0] : 0.f;
                float b1 = (bias && c0 + 1 < nBias) ? bias[c0 + 1] : 0.f;
                float2 v0 = make_float2(acc[mt][nt][0] + b0, acc[mt][nt][1] + b1);
                float2 v1 = make_float2(acc[mt][nt][2] + b0, acc[mt][nt][3] + b1);
                *reinterpret_cast<float2*>(&Cc[(size_t)r0 * Nn + c0]) = v0;
                *reinterpret_cast<float2*>(&Cc[(size_t)(r0 + 8) * Nn + c0]) = v1;
            }
        }
    }
}

// ---------------- dedicated N=3, K=832 GEMM (offset convs of k=1 layers) ------
__global__ void k_gemm_n3(const float* __restrict__ A, const float* __restrict__ Bm,
                          const float* __restrict__ bias, float* __restrict__ out) {
    __shared__ float Bs[832 * 3];
    int tid = threadIdx.x;
    for (int i = tid; i < 832 * 3; i += 256) Bs[i] = Bm[i];
    __syncthreads();
    int warp = tid >> 5, lane = tid & 31;
    int m = blockIdx.x * 8 + warp;
    const float4* aRow = reinterpret_cast<const float4*>(A + (size_t)m * 832);
    float s0 = 0.f, s1 = 0.f, s2 = 0.f;
    #pragma unroll
    for (int j = 0; j < 7; j++) {
        int q = lane + j * 32;
        if (q < 208) {
            float4 v = aRow[q];
            int k = q * 4;
            s0 = fmaf(v.x, Bs[(k+0)*3+0], s0); s1 = fmaf(v.x, Bs[(k+0)*3+1], s1); s2 = fmaf(v.x, Bs[(k+0)*3+2], s2);
            s0 = fmaf(v.y, Bs[(k+1)*3+0], s0); s1 = fmaf(v.y, Bs[(k+1)*3+1], s1); s2 = fmaf(v.y, Bs[(k+1)*3+2], s2);
            s0 = fmaf(v.z, Bs[(k+2)*3+0], s0); s1 = fmaf(v.z, Bs[(k+2)*3+1], s1); s2 = fmaf(v.z, Bs[(k+2)*3+2], s2);
            s0 = fmaf(v.w, Bs[(k+3)*3+0], s0); s1 = fmaf(v.w, Bs[(k+3)*3+1], s1); s2 = fmaf(v.w, Bs[(k+3)*3+2], s2);
        }
    }
    #pragma unroll
    for (int o = 16; o; o >>= 1) {
        s0 += __shfl_xor_sync(0xffffffffu, s0, o);
        s1 += __shfl_xor_sync(0xffffffffu, s1, o);
        s2 += __shfl_xor_sync(0xffffffffu, s2, o);
    }
    if (lane == 0) {
        out[(size_t)m * 3 + 0] = s0 + bias[0];
        out[(size_t)m * 3 + 1] = s1 + bias[1];
        out[(size_t)m * 3 + 2] = s2 + bias[2];
    }
}

// ---------------- k=1 trilinear sampling (one tap) ----------------------------
__global__ void k_sample(const float* __restrict__ src, const float* __restrict__ off,
                         float* __restrict__ samp, int C) {
    int m  = blockIdx.x;
    int b = m / SPA, s = m - b * SPA;
    int t = s / (HH * WW); int rem = s - t * HH * WW;
    int h = rem / WW, w = rem - h * WW;
    const float* op = off + (size_t)m * 3;
    float tc = (float)t + op[0];
    float hc = (float)h + op[1];
    float wc = (float)w + op[2];
    float tf = floorf(tc), hf = floorf(hc), wf = floorf(wc);
    float ft = tc - tf, fh = hc - hf, fw = wc - wf;
    int t0 = (int)tf, h0 = (int)hf, w0 = (int)wf;

    float wgt[8]; const float* ptr[8];
    #pragma unroll
    for (int ci = 0; ci < 8; ci++) {
        int dt = ci >> 2, dh = (ci >> 1) & 1, dw = ci & 1;
        int ti = t0 + dt, hi = h0 + dh, wi = w0 + dw;
        bool valid = (ti >= 0) && (ti < TT) && (hi >= 0) && (hi < HH) && (wi >= 0) && (wi < WW);
        float wv = (dt ? ft : 1.f - ft) * (dh ? fh : 1.f - fh) * (dw ? fw : 1.f - fw);
        wgt[ci] = valid ? wv : 0.f;
        int tic = min(max(ti, 0), TT - 1);
        int hic = min(max(hi, 0), HH - 1);
        int wic = min(max(wi, 0), WW - 1);
        ptr[ci] = src + ((size_t)b * SPA + (tic * HH + hic) * WW + wic) * C;
    }
    float* dst = samp + (size_t)m * C;
    for (int c = threadIdx.x * 4; c < C; c += blockDim.x * 4) {
        float4 acc = make_float4(0.f, 0.f, 0.f, 0.f);
        #pragma unroll
        for (int ci = 0; ci < 8; ci++) {
            float4 v = *reinterpret_cast<const float4*>(ptr[ci] + c);
            acc.x = fmaf(wgt[ci], v.x, acc.x);
            acc.y = fmaf(wgt[ci], v.y, acc.y);
            acc.z = fmaf(wgt[ci], v.z, acc.z);
            acc.w = fmaf(wgt[ci], v.w, acc.w);
        }
        acc.x = f2tff(acc.x); acc.y = f2tff(acc.y);
        acc.z = f2tff(acc.z); acc.w = f2tff(acc.w);
        *reinterpret_cast<float4*>(dst + c) = acc;
    }
}

// ---------------- k=3 trilinear sampling: one CTA per position, 27 taps -------
__global__ void k_sample3(const float* __restrict__ src, const float* __restrict__ off,
                          float* __restrict__ samp, int C) {
    __shared__ float sw[27][8];
    __shared__ int   sb[27][8];
    int m = blockIdx.x;
    int b = m / SPA, s = m - b * SPA;
    int t = s / (HH * WW); int rem = s - t * HH * WW;
    int h = rem / WW, w = rem - h * WW;
    int tid = threadIdx.x;
    if (tid < 27) {
        int kt = tid / 9, kh = (tid / 3) % 3, kw = tid % 3;
        const float* op = off + (size_t)m * 96 + tid * 3;
        float tc = (float)(t - 1 + kt) + op[0];
        float hc = (float)(h - 1 + kh) + op[1];
        float wc = (float)(w - 1 + kw) + op[2];
        float tf = floorf(tc), hf = floorf(hc), wf = floorf(wc);
        float ft = tc - tf, fh = hc - hf, fw = wc - wf;
        int t0 = (int)tf, h0 = (int)hf, w0 = (int)wf;
        #pragma unroll
        for (int ci = 0; ci < 8; ci++) {
            int dt = ci >> 2, dh = (ci >> 1) & 1, dw = ci & 1;
            int ti = t0 + dt, hi = h0 + dh, wi = w0 + dw;
            bool valid = (ti >= 0) && (ti < TT) && (hi >= 0) && (hi < HH) && (wi >= 0) && (wi < WW);
            float wv = (dt ? ft : 1.f - ft) * (dh ? fh : 1.f - fh) * (dw ? fw : 1.f - fw);
            sw[tid][ci] = valid ? wv : 0.f;
            int tic = min(max(ti, 0), TT - 1);
            int hic = min(max(hi, 0), HH - 1);
            int wic = min(max(wi, 0), WW - 1);
            sb[tid][ci] = b * SPA + (tic * HH + hic) * WW + wic;
        }
    }
    __syncthreads();
    int nC4 = C >> 2;
    int items = 27 * nC4;
    float* dst = samp + (size_t)m * 27 * C;
    for (int it = tid; it < items; it += blockDim.x) {
        int kk = it / nC4, c4 = it - kk * nC4;
        float4 acc = make_float4(0.f, 0.f, 0.f, 0.f);
        #pragma unroll
        for (int ci = 0; ci < 8; ci++) {
            float wv = sw[kk][ci];
            const float4* p = reinterpret_cast<const float4*>(src + (size_t)sb[kk][ci] * C) + c4;
            float4 v = *p;
            acc.x = fmaf(wv, v.x, acc.x);
            acc.y = fmaf(wv, v.y, acc.y);
            acc.z = fmaf(wv, v.z, acc.z);
            acc.w = fmaf(wv, v.w, acc.w);
        }
        acc.x = f2tff(acc.x); acc.y = f2tff(acc.y);
        acc.z = f2tff(acc.z); acc.w = f2tff(acc.w);
        reinterpret_cast<float4*>(dst)[(size_t)kk * nC4 + c4] = acc;
    }
}

// ---------------- k=3 im2col: one CTA per position, 27 taps -------------------
__global__ void k_im2col3(const float* __restrict__ src, float* __restrict__ outm, int C) {
    __shared__ int sidx[27];
    __shared__ int svalid[27];
    int m = blockIdx.x;
    int b = m / SPA, s = m - b * SPA;
    int t = s / (HH * WW); int rem = s - t * HH * WW;
    int h = rem / WW, w = rem - h * WW;
    int tid = threadIdx.x;
    if (tid < 27) {
        int kt = tid / 9, kh = (tid / 3) % 3, kw = tid % 3;
        int ti = t + kt - 1, hi = h + kh - 1, wi = w + kw - 1;
        bool valid = (ti >= 0) && (ti < TT) && (hi >= 0) && (hi < HH) && (wi >= 0) && (wi < WW);
        svalid[tid] = valid;
        sidx[tid] = b * SPA + (valid ? (ti * HH + hi) * WW + wi : 0);
    }
    __syncthreads();
    int nC4 = C >> 2;
    int items = 27 * nC4;
    float* dst = outm + (size_t)m * 27 * C;
    for (int it = tid; it < items; it += blockDim.x) {
        int kk = it / nC4, c4 = it - kk * nC4;
        float4 v = make_float4(0.f, 0.f, 0.f, 0.f);
        if (svalid[kk])
            v = reinterpret_cast<const float4*>(src + (size_t)sidx[kk] * C)[c4];
        v.x = f2tff(v.x); v.y = f2tff(v.y);
        v.z = f2tff(v.z); v.w = f2tff(v.w);
        reinterpret_cast<float4*>(dst)[(size_t)kk * nC4 + c4] = v;
    }
}

// ---------------- per-channel batch stats (mean, biased var) ------------------
__global__ void k_stats(const float* __restrict__ Cm, float* __restrict__ stats, int Nn) {
    int n = blockIdx.x * 32 + threadIdx.x;
    float s = 0.f, s2 = 0.f;
    if (n < Nn) {
        for (int m = threadIdx.y; m < MTOT; m += 8) {
            float v = Cm[(size_t)m * Nn + n];
            s += v; s2 += v * v;
        }
    }
    __shared__ float sh[8][32], sh2[8][32];
    sh[threadIdx.y][threadIdx.x] = s;
    sh2[threadIdx.y][threadIdx.x] = s2;
    __syncthreads();
    if (threadIdx.y == 0 && n < Nn) {
        #pragma unroll
        for (int i = 1; i < 8; i++) { s += sh[i][threadIdx.x]; s2 += sh2[i][threadIdx.x]; }
        float mean = s / (float)MTOT;
        float var  = s2 / (float)MTOT - mean * mean;
        stats[n]       = mean;
        stats[512 + n] = var;
    }
}

// ---------------- BN + ReLU, channels-last output (intermediates) -------------
__global__ void k_bnout_cl(const float* __restrict__ Cm, const float* __restrict__ stats,
                           const float* __restrict__ gamma, const float* __restrict__ beta,
                           float* __restrict__ outp, int Nn) {
    size_t idx = (size_t)blockIdx.x * blockDim.x + threadIdx.x;
    size_t tot = (size_t)MTOT * Nn;
    if (idx >= tot) return;
    int n = (int)(idx % Nn);
    float sc = gamma[n] * rsqrtf(stats[512 + n] + 1e-5f);
    float v  = fmaf(Cm[idx] - stats[n], sc, beta[n]);
    outp[idx] = fmaxf(v, 0.f);
}

// ---------------- BN + ReLU + tiled transpose into NCDHW concat output --------
__global__ void k_bnout_t(const float* __restrict__ Cm, const float* __restrict__ stats,
                          const float* __restrict__ gamma, const float* __restrict__ beta,
                          float* __restrict__ outp, int Nn, int ch0) {
    __shared__ float tile[32][33];
    int b = blockIdx.z, s0 = blockIdx.x * 32, n0 = blockIdx.y * 32;
    int tx = threadIdx.x, ty = threadIdx.y;
    int n = n0 + tx;
    float mean = stats[n];
    float sc = gamma[n] * rsqrtf(stats[512 + n] + 1e-5f);
    float bt = beta[n];
    #pragma unroll
    for (int i = ty; i < 32; i += 8) {
        float v = fmaf(Cm[((size_t)b * SPA + s0 + i) * Nn + n] - mean, sc, bt);
        tile[i][tx] = fmaxf(v, 0.f);
    }
    __syncthreads();
    #pragma unroll
    for (int i = ty; i < 32; i += 8)
        outp[((size_t)b * 832 + ch0 + n0 + i) * SPA + s0 + tx] = tile[tx][i];
}

// ============================ host orchestration ==============================
static const int GEMM_SMEM = (2 * 128 * 36 + 2 * 32 * 132) * 4;  // 70,656 B

static void run_gemm_pipe(const float* A, const float* Bm, const float* bias, int nBias,
                          float* C, int Nn, int Kn) {
    static bool attrSet = false;
    if (!attrSet) {
        cudaFuncSetAttribute(k_gemm_pipe, cudaFuncAttributeMaxDynamicSharedMemorySize, GEMM_SMEM);
        attrSet = true;
    }
    dim3 grid((Nn + 127) / 128, MTOT / 128);
    k_gemm_pipe<<<grid, 256, GEMM_SMEM>>>(A, Bm, bias, nBias, C, Nn, Kn);
}

static void run_bn(const float* conv, float* stats, const float* g, const float* bt,
                   float* outp, int Cout, int mode, int ch0) {
    k_stats<<<(Cout + 31) / 32, dim3(32, 8)>>>(conv, stats, Cout);
    if (mode == 0) {
        size_t tot = (size_t)MTOT * Cout;
        k_bnout_cl<<<(unsigned)((tot + 255) / 256), 256>>>(conv, stats, g, bt, outp, Cout);
    } else {
        dim3 grid(SPA / 32, Cout / 32, BB);
        k_bnout_t<<<grid, dim3(32, 8)>>>(conv, stats, g, bt, outp, Cout, ch0);
    }
}

static void run_k1(const float* srcT, int Cin, int Cout,
                   const float* woffT, const float* boffp, const float* wTp,
                   const float* g, const float* bt,
                   float* offb, float* samp, float* conv, float* stats,
                   float* outp, int mode, int ch0) {
    k_gemm_n3<<<MTOT / 8, 256>>>(srcT, woffT, boffp, offb);          // Cin == 832 always
    k_sample<<<MTOT, 128>>>(srcT, offb, samp, Cin);
    run_gemm_pipe(samp, wTp, nullptr, 0, conv, Cout, Cin);
    run_bn(conv, stats, g, bt, outp, Cout, mode, ch0);
}

static void run_k3(const float* srcT, int Cin, int Cout,
                   const float* woffT, const float* boffp, const float* wTp,
                   const float* g, const float* bt,
                   float* offb, float* samp, float* conv, float* stats,
                   float* outp, int mode, int ch0) {
    int Kd = 27 * Cin;
    int blk = (Cin >= 128) ? 256 : 128;
    k_im2col3<<<MTOT, blk>>>(srcT, samp, Cin);
    run_gemm_pipe(samp, woffT, boffp, 81, offb, 96, Kd);   // offsets padded N=96
    k_sample3<<<MTOT, blk>>>(srcT, offb, samp, Cin);
    run_gemm_pipe(samp, wTp, nullptr, 0, conv, Cout, Kd);
    run_bn(conv, stats, g, bt, outp, Cout, mode, ch0);
}

extern "C" void kernel_launch(void* const* d_in, const int* in_sizes, int n_in,
                              void* d_out, int out_size) {
    const float* x = (const float*)d_in[0];
    const float *woff[6], *boff[6], *wcv[6], *gam[6], *bet[6];
    for (int i = 0; i < 6; i++) {
        woff[i] = (const float*)d_in[1 + 5 * i];
        boff[i] = (const float*)d_in[2 + 5 * i];
        wcv[i]  = (const float*)d_in[3 + 5 * i];
        gam[i]  = (const float*)d_in[4 + 5 * i];
        bet[i]  = (const float*)d_in[5 + 5 * i];
    }
    float *xT, *xmT, *x1a, *x2a, *samp, *conv, *offb, *stats, *wT, *woffT;
    cudaGetSymbolAddress((void**)&xT,    g_xT);
    cudaGetSymbolAddress((void**)&xmT,   g_xmT);
    cudaGetSymbolAddress((void**)&x1a,   g_x1a);
    cudaGetSymbolAddress((void**)&x2a,   g_x2a);
    cudaGetSymbolAddress((void**)&samp,  g_samp);
    cudaGetSymbolAddress((void**)&conv,  g_conv);
    cudaGetSymbolAddress((void**)&offb,  g_offb);
    cudaGetSymbolAddress((void**)&stats, g_stats);
    cudaGetSymbolAddress((void**)&wT,    g_wT);
    cudaGetSymbolAddress((void**)&woffT, g_woffT);
    float* out = (float*)d_out;

    const int CIN[6]  = {832, 832, 160, 832, 32, 832};
    const int COUT[6] = {256, 160, 320, 32, 128, 128};
    const int KK[6]   = {1, 1, 27, 1, 27, 1};
    size_t wtoff[6], wooff[6];
    {
        size_t a = 0, bsz = 0;
        for (int i = 0; i < 6; i++) { wtoff[i] = a; a += (size_t)KK[i] * CIN[i] * COUT[i]; }
        for (int i = 0; i < 6; i++) {
            wooff[i] = bsz;
            bsz += (KK[i] == 1) ? (size_t)CIN[i] * 3 : (size_t)KK[i] * CIN[i] * 96;
        }
    }

    // launch #1: fused prep (transpose + all 12 weight transposes)
    {
        WJobs jb;
        int pos = 0;
        for (int i = 0; i < 6; i++) {
            jb.src[i] = wcv[i]; jb.dst[i] = wT + wtoff[i];
            jb.cout[i] = COUT[i]; jb.coutpad[i] = COUT[i];
            jb.cin[i] = CIN[i]; jb.kk[i] = KK[i]; jb.cvt[i] = 1;
            jb.start[i] = pos; pos += KK[i] * CIN[i] * COUT[i];
        }
        for (int i = 0; i < 6; i++) {
            int j = 6 + i;
            jb.src[j] = woff[i]; jb.dst[j] = woffT + wooff[i];
            if (KK[i] == 1) { jb.cout[j] = 3;  jb.coutpad[j] = 3;  jb.cvt[j] = 0; }
            else            { jb.cout[j] = 81; jb.coutpad[j] = 96; jb.cvt[j] = 1; }
            jb.cin[j] = CIN[i]; jb.kk[j] = KK[i];
            jb.start[j] = pos;
            pos += (KK[i] == 1) ? CIN[i] * 3 : KK[i] * CIN[i] * 96;
        }
        jb.start[12] = pos;
        int wBlocks = (pos + 255) / 256;
        k_prep<<<NT_BLOCKS + wBlocks, 256>>>(jb, x, xT);
    }

    // branch 0 (launches #2 n3, #3 sample, #4 gemm_pipe -> profiled)
    run_k1(xT, 832, 256, woffT + wooff[0], boff[0], wT + wtoff[0], gam[0], bet[0],
           offb, samp, conv, stats, out, 1, 0);

    // branch 1
    run_k1(xT, 832, 160, woffT + wooff[1], boff[1], wT + wtoff[1], gam[1], bet[1],
           offb, samp, conv, stats, x1a, 0, 0);
    run_k3(x1a, 160, 320, woffT + wooff[2], boff[2], wT + wtoff[2], gam[2], bet[2],
           offb, samp, conv, stats, out, 1, 256);

    // branch 2
    run_k1(xT, 832, 32, woffT + wooff[3], boff[3], wT + wtoff[3], gam[3], bet[3],
           offb, samp, conv, stats, x2a, 0, 0);
    run_k3(x2a, 32, 128, woffT + wooff[4], boff[4], wT + wtoff[4], gam[4], bet[4],
           offb, samp, conv, stats, out, 1, 576);

    // branch 3: separable maxpool -> deform k=1
    {
        float* tmp1 = samp;
        float* tmp2 = samp + (size_t)MTOT * 832;
        int nthr = (int)(((size_t)MTOT * 208 + 255) / 256);
        k_max3<<<nthr, 256>>>(xT,   tmp1, 1,       WW);
        k_max3<<<nthr, 256>>>(tmp1, tmp2, WW,      HH);
        k_max3<<<nthr, 256>>>(tmp2, xmT,  HH * WW, TT);
    }
    run_k1(xmT, 832, 128, woffT + wooff[5], boff[5], wT + wtoff[5], gam[5], bet[5],
           offb, samp, conv, stats, out, 1, 704);
}